// round 12
// baseline (speedup 1.0000x reference)
#include <cuda_runtime.h>
#include <cuda_fp16.h>
#include <math.h>

#define BSZ 4
#define SEQ 2048
#define NH  16
#define HD  64
#define DM  1024
#define EXP_C 0.1803368801f   // 0.125 * log2(e), folded into q at the producer

// Scratch (device globals; no allocations allowed). All tensor operands fp16.
__device__ __half  g_x [BSZ*SEQ*DM];
__device__ __half  g_wq[3*DM*DM];
__device__ __half  g_wo[DM*DM];
__device__ __half  g_q [BSZ*NH*SEQ*HD];   // pre-scaled by EXP_C
__device__ __half  g_k [BSZ*NH*SEQ*HD];
__device__ __half  g_vt[BSZ*NH*HD*SEQ];   // V transposed: [bh][d][s]
__device__ __half  g_ao[BSZ*SEQ*DM];
__device__ float2  g_rope[SEQ*32];        // (cos,sin) per (pos, pair)

// ---------------------------------------------------------------------------
__device__ __forceinline__ unsigned packh2(float lo, float hi) {
    __half2 h = __floats2half2_rn(lo, hi);
    return *(unsigned*)&h;
}
// half2 MUFU exp2: one instruction, two values, result already packed fp16.
__device__ __forceinline__ unsigned h2ex2(unsigned x) {
    unsigned r; asm("ex2.approx.f16x2 %0, %1;" : "=r"(r) : "r"(x)); return r;
}
__device__ __forceinline__ __half2 u2h(unsigned x) { return *(__half2*)&x; }

__device__ __forceinline__ unsigned saddr(const void* p) {
    return (unsigned)__cvta_generic_to_shared(p);
}
__device__ __forceinline__ void cp16(unsigned d, const void* s) {
    asm volatile("cp.async.cg.shared.global [%0], [%1], 16;" :: "r"(d), "l"(s));
}
#define CP_COMMIT() asm volatile("cp.async.commit_group;")
#define CP_WAIT(n)  asm volatile("cp.async.wait_group %0;" :: "n"(n))

__device__ __forceinline__ void ldsm_x4(unsigned& r0, unsigned& r1,
                                        unsigned& r2, unsigned& r3, unsigned a) {
    asm volatile("ldmatrix.sync.aligned.m8n8.x4.shared.b16 {%0,%1,%2,%3}, [%4];"
                 : "=r"(r0), "=r"(r1), "=r"(r2), "=r"(r3) : "r"(a));
}
// fp16 mma, fp32 accumulate: D[16x8] += A[16x16] B[16x8]
__device__ __forceinline__ void mma_f16(float* c, const unsigned* a, const unsigned* b) {
    asm volatile("mma.sync.aligned.m16n8k16.row.col.f32.f16.f16.f32 "
                 "{%0,%1,%2,%3},{%4,%5,%6,%7},{%8,%9},{%0,%1,%2,%3};"
                 : "+f"(c[0]), "+f"(c[1]), "+f"(c[2]), "+f"(c[3])
                 : "r"(a[0]), "r"(a[1]), "r"(a[2]), "r"(a[3]), "r"(b[0]), "r"(b[1]));
}

// ---------------------------------------------------------------------------
__global__ void rope_init() {
    int i = blockIdx.x * 256 + threadIdx.x;   // SEQ*32 entries
    int m = i >> 5, p = i & 31;
    float theta = powf(10000.0f, -(float)p / 32.0f);
    float s, c; sincosf((float)m * theta, &s, &c);
    g_rope[i] = make_float2(c, s);
}

// Convert x / W_qkv / W_out to fp16 (RN). Unit of work: 8 elements.
#define NX8  (BSZ*SEQ*DM/8)
#define NWQ8 (3*DM*DM/8)
#define NWO8 (DM*DM/8)
__global__ __launch_bounds__(256) void tohalf_kernel(
    const float4* __restrict__ x, const float4* __restrict__ wq,
    const float4* __restrict__ wo)
{
    int i = blockIdx.x * 256 + threadIdx.x;
    const float4* src; __half* dst; int o;
    if (i < NX8)              { src = x;  dst = g_x;  o = i; }
    else if (i < NX8 + NWQ8)  { src = wq; dst = g_wq; o = i - NX8; }
    else                      { src = wo; dst = g_wo; o = i - NX8 - NWQ8; }
    float4 a = src[(size_t)o * 2], b = src[(size_t)o * 2 + 1];
    __half2 h[4];
    h[0] = __floats2half2_rn(a.x, a.y); h[1] = __floats2half2_rn(a.z, a.w);
    h[2] = __floats2half2_rn(b.x, b.y); h[3] = __floats2half2_rn(b.z, b.w);
    *(uint4*)(dst + (size_t)o * 8) = *(uint4*)h;
}

// ---------------------------------------------------------------------------
// GEMM core (fp16): C = A @ B^T, CTA tile 128x128, k-chunk 64 (4 x k16 mma),
// 16 chunks FULLY UNROLLED, 3-stage cp.async pipeline, one barrier per chunk.
// ---------------------------------------------------------------------------
#define GEMM_SMEM (6*128*72*2)

#define GEMM_PREFETCH(st, k0)                                                  \
    do {                                                                       \
        _Pragma("unroll")                                                      \
        for (int i_ = 0; i_ < 4; i_++) {                                       \
            int r_ = cr + i_ * 32;                                             \
            cp16(saddr(&As[st][r_][cq]), Abase + (size_t)r_ * DM + (k0) + cq); \
            cp16(saddr(&Bs[st][r_][cq]), Bbase + (size_t)r_ * DM + (k0) + cq); \
        }                                                                      \
        CP_COMMIT();                                                           \
    } while (0)

#define GEMM_PIPELINE(AbaseE, BbaseE)                                          \
    const int lane = threadIdx.x & 31;                                         \
    const int wid  = threadIdx.x >> 5;                                         \
    const int wm = wid >> 2, wn = wid & 3;                                     \
    extern __shared__ __half hsm[];                                            \
    __half (*As)[128][72] = (__half(*)[128][72])(hsm);                         \
    __half (*Bs)[128][72] = (__half(*)[128][72])(hsm + 3*128*72);              \
    float acc[4][4][4] = {};                                                   \
    const int cr = threadIdx.x >> 3;        /* 0..31 */                        \
    const int cq = (threadIdx.x & 7) * 8;   /* halves, 16B granule */          \
    const __half* Abase = (AbaseE);                                            \
    const __half* Bbase = (BbaseE);                                            \
    GEMM_PREFETCH(0, 0);                                                       \
    GEMM_PREFETCH(1, 64);                                                      \
    _Pragma("unroll")                                                          \
    for (int it = 0; it < 16; it++) {                                          \
        if (it + 2 < 16) { CP_WAIT(1); } else { CP_WAIT(0); }                  \
        __syncthreads();                                                       \
        if (it + 2 < 16) GEMM_PREFETCH((it + 2) % 3, (it + 2) * 64);           \
        const int cur = it % 3;                                                \
        _Pragma("unroll")                                                      \
        for (int kk = 0; kk < 4; kk++) {                                       \
            const int koff = kk*16 + ((lane >> 4) << 3);                       \
            unsigned a[4][4];                                                  \
            _Pragma("unroll")                                                  \
            for (int ma = 0; ma < 4; ma++)                                     \
                ldsm_x4(a[ma][0], a[ma][1], a[ma][2], a[ma][3],                \
                        saddr(&As[cur][wm*64 + ma*16 + (lane & 15)][koff]));   \
            unsigned b[4][2];                                                  \
            _Pragma("unroll")                                                  \
            for (int pr = 0; pr < 2; pr++) {                                   \
                unsigned r0, r1, r2, r3;                                       \
                ldsm_x4(r0, r1, r2, r3,                                        \
                        saddr(&Bs[cur][wn*32 + pr*16 + (lane & 15)][koff]));   \
                b[pr*2][0]   = r0; b[pr*2][1]   = r2;                          \
                b[pr*2+1][0] = r1; b[pr*2+1][1] = r3;                          \
            }                                                                  \
            _Pragma("unroll")                                                  \
            for (int ma = 0; ma < 4; ma++)                                     \
                _Pragma("unroll")                                              \
                for (int na = 0; na < 4; na++)                                 \
                    mma_f16(acc[ma][na], a[ma], b[na]);                        \
        }                                                                      \
    }

// ---------------------------------------------------------------------------
// QKV GEMM + bias + RoPE + scatter (fp16 outputs; V transposed).
// Q is additionally scaled by EXP_C so flash's exp is a bare ex2.
// ---------------------------------------------------------------------------
__global__ __launch_bounds__(256, 2) void qkv_kernel(const float* __restrict__ bias)
{
    const int m0 = blockIdx.y * 128;
    const int n0 = blockIdx.x * 128;

    GEMM_PIPELINE(g_x + (size_t)m0 * DM, g_wq + (size_t)n0 * DM)

    const int gid = lane >> 2, tig = lane & 3;
    const int which = n0 >> 10;                         // 0=q,1=k,2=v
    const int bq = m0 >> 11;
    const int s_base = (m0 & (SEQ-1)) + wm * 64;
    const int col_local = (n0 & 1023) + wn * 32;
    const int head = col_local >> 6;
    const int d0 = col_local & 63;
    const size_t bh = (size_t)(bq * NH + head);
    const float qscale = (which == 0) ? EXP_C : 1.0f;

    #pragma unroll
    for (int na = 0; na < 4; na++) {
        const int d = d0 + na*8 + 2*tig;
        const int ncol_g = n0 + wn*32 + na*8 + 2*tig;
        const float b0v = bias[ncol_g], b1v = bias[ncol_g + 1];
        const int p = d >> 1;
        #pragma unroll
        for (int ma = 0; ma < 4; ma++) {
            int s_lo = s_base + ma*16 + gid;
            float v0 = acc[ma][na][0] + b0v;
            float v1 = acc[ma][na][1] + b1v;
            float u0 = acc[ma][na][2] + b0v;
            float u1 = acc[ma][na][3] + b1v;
            if (which == 2) {
                __half* vt = g_vt + bh * (size_t)(HD * SEQ);
                vt[(size_t)d     * SEQ + s_lo    ] = __float2half_rn(v0);
                vt[(size_t)(d+1) * SEQ + s_lo    ] = __float2half_rn(v1);
                vt[(size_t)d     * SEQ + s_lo + 8] = __float2half_rn(u0);
                vt[(size_t)(d+1) * SEQ + s_lo + 8] = __float2half_rn(u1);
            } else {
                __half* dst = (which == 0 ? g_q : g_k) + bh * (size_t)(SEQ * HD);
                float2 rl = g_rope[s_lo * 32 + p];
                float2 rh = g_rope[(s_lo + 8) * 32 + p];
                *(__half2*)&dst[(size_t)s_lo * HD + d] =
                    __floats2half2_rn((v0*rl.x - v1*rl.y) * qscale,
                                      (v1*rl.x + v0*rl.y) * qscale);
                *(__half2*)&dst[(size_t)(s_lo+8) * HD + d] =
                    __floats2half2_rn((u0*rh.x - u1*rh.y) * qscale,
                                      (u1*rh.x + u0*rh.y) * qscale);
            }
        }
    }
}

// ---------------------------------------------------------------------------
// Out-proj GEMM: out(fp32) = g_ao @ W_out^T + b_out
// ---------------------------------------------------------------------------
__global__ __launch_bounds__(256, 2) void out_kernel(
    const float* __restrict__ bias, float* __restrict__ out)
{
    const int m0 = blockIdx.y * 128;
    const int n0 = blockIdx.x * 128;

    GEMM_PIPELINE(g_ao + (size_t)m0 * DM, g_wo + (size_t)n0 * DM)

    const int gid = lane >> 2, tig = lane & 3;
    #pragma unroll
    for (int na = 0; na < 4; na++) {
        int col = n0 + wn*32 + na*8 + 2*tig;
        float b0v = bias[col], b1v = bias[col + 1];
        #pragma unroll
        for (int ma = 0; ma < 4; ma++) {
            int row = m0 + wm*64 + ma*16 + gid;
            out[(size_t)row       * DM + col    ] = acc[ma][na][0] + b0v;
            out[(size_t)row       * DM + col + 1] = acc[ma][na][1] + b1v;
            out[(size_t)(row + 8) * DM + col    ] = acc[ma][na][2] + b0v;
            out[(size_t)(row + 8) * DM + col + 1] = acc[ma][na][3] + b1v;
        }
    }
}

// ---------------------------------------------------------------------------
// Flash attention v8: 8 warps x 32 q-rows, Q + P fragments in registers,
// 64-key double-buffered K/V tiles, one barrier per 64 keys.
// exp via ex2.approx.f16x2 (HALF the MUFU instructions; result IS the PV
// fragment). Row sums accumulate in half2 (HADD2 tree, same fp16 values the
// mma consumes) and flush to fp32 once per 64-key tile.
// smem halves: Qs[256][72] | Ks[2][64][72] | Vs[2][64][72]  = 73728 bytes
// ---------------------------------------------------------------------------
#define FLH_K  (256*72)
#define FLH_V  (FLH_K + 2*64*72)
#define FL_SMEM ((FLH_V + 2*64*72) * 2)   // 73728 bytes

// One 32-key half: keys H..H+31 of the CUR buffer.
#define FLASH_HALF(CUR, H)                                                    \
    {                                                                         \
        float S[2][4][4] = {};                                                \
        /* ---- S_A: keys H+0..H+15 ---- */                                   \
        _Pragma("unroll")                                                     \
        for (int kk = 0; kk < 4; kk++) {                                      \
            const int koff = kk*16 + ((lane >> 4) << 3);                      \
            unsigned r0, r1, r2, r3;                                          \
            ldsm_x4(r0, r1, r2, r3,                                           \
                    saddr(&Ks[CUR][(H) + (lane & 15)][koff]));                \
            unsigned b0[2] = {r0, r2}, b1[2] = {r1, r3};                      \
            _Pragma("unroll")                                                 \
            for (int t = 0; t < 2; t++) {                                     \
                mma_f16(S[t][0], aq[t][kk], b0);                              \
                mma_f16(S[t][1], aq[t][kk], b1);                              \
            }                                                                 \
        }                                                                     \
        /* ---- S_B: keys H+16..H+31 ---- */                                  \
        _Pragma("unroll")                                                     \
        for (int kk = 0; kk < 4; kk++) {                                      \
            const int koff = kk*16 + ((lane >> 4) << 3);                      \
            unsigned r0, r1, r2, r3;                                          \
            ldsm_x4(r0, r1, r2, r3,                                           \
                    saddr(&Ks[CUR][(H) + 16 + (lane & 15)][koff]));           \
            unsigned b0[2] = {r0, r2}, b1[2] = {r1, r3};                      \
            _Pragma("unroll")                                                 \
            for (int t = 0; t < 2; t++) {                                     \
                mma_f16(S[t][2], aq[t][kk], b0);                              \
                mma_f16(S[t][3], aq[t][kk], b1);                              \
            }                                                                 \
        }                                                                     \
        /* ---- exp_A: half2 ex2 -> PV A-fragments + HADD2 row sums ---- */   \
        unsigned pa[2][4];                                                    \
        _Pragma("unroll")                                                     \
        for (int t = 0; t < 2; t++) {                                         \
            pa[t][0] = h2ex2(packh2(S[t][0][0], S[t][0][1]));                 \
            pa[t][1] = h2ex2(packh2(S[t][0][2], S[t][0][3]));                 \
            pa[t][2] = h2ex2(packh2(S[t][1][0], S[t][1][1]));                 \
            pa[t][3] = h2ex2(packh2(S[t][1][2], S[t][1][3]));                 \
            racc[t][0] = __hadd2(racc[t][0], __hadd2(u2h(pa[t][0]), u2h(pa[t][2]))); \
            racc[t][1] = __hadd2(racc[t][1], __hadd2(u2h(pa[t][1]), u2h(pa[t][3]))); \
        }                                                                     \
        /* ---- PV_A: V s-cols H..H+15 ---- */                                \
        {                                                                     \
            const int koff = (H) + ((lane >> 4) << 3);                        \
            _Pragma("unroll")                                                 \
            for (int pr = 0; pr < 4; pr++) {                                  \
                unsigned r0, r1, r2, r3;                                      \
                ldsm_x4(r0, r1, r2, r3,                                       \
                        saddr(&Vs[CUR][pr*16 + (lane & 15)][koff]));          \
                unsigned b0[2] = {r0, r2}, b1[2] = {r1, r3};                  \
                _Pragma("unroll")                                             \
                for (int t = 0; t < 2; t++) {                                 \
                    mma_f16(O[t][pr*2],   pa[t], b0);                         \
                    mma_f16(O[t][pr*2+1], pa[t], b1);                         \
                }                                                             \
            }                                                                 \
        }                                                                     \
        /* ---- exp_B: second 16 keys, overlaps PV_A ---- */                  \
        unsigned pb[2][4];                                                    \
        _Pragma("unroll")                                                     \
        for (int t = 0; t < 2; t++) {                                         \
            pb[t][0] = h2ex2(packh2(S[t][2][0], S[t][2][1]));                 \
            pb[t][1] = h2ex2(packh2(S[t][2][2], S[t][2][3]));                 \
            pb[t][2] = h2ex2(packh2(S[t][3][0], S[t][3][1]));                 \
            pb[t][3] = h2ex2(packh2(S[t][3][2], S[t][3][3]));                 \
            racc[t][0] = __hadd2(racc[t][0], __hadd2(u2h(pb[t][0]), u2h(pb[t][2]))); \
            racc[t][1] = __hadd2(racc[t][1], __hadd2(u2h(pb[t][1]), u2h(pb[t][3]))); \
        }                                                                     \
        /* ---- PV_B: V s-cols H+16..H+31 ---- */                             \
        {                                                                     \
            const int koff = (H) + 16 + ((lane >> 4) << 3);                   \
            _Pragma("unroll")                                                 \
            for (int pr = 0; pr < 4; pr++) {                                  \
                unsigned r0, r1, r2, r3;                                      \
                ldsm_x4(r0, r1, r2, r3,                                       \
                        saddr(&Vs[CUR][pr*16 + (lane & 15)][koff]));          \
                unsigned b0[2] = {r0, r2}, b1[2] = {r1, r3};                  \
                _Pragma("unroll")                                             \
                for (int t = 0; t < 2; t++) {                                 \
                    mma_f16(O[t][pr*2],   pb[t], b0);                         \
                    mma_f16(O[t][pr*2+1], pb[t], b1);                         \
                }                                                             \
            }                                                                 \
        }                                                                     \
    }

// One 64-key tile: wait, prefetch next buffer, compute two halves, flush rs.
#define FLASH_TILE(CUR, IT)                                                   \
    {                                                                         \
        CP_WAIT(0);                                                           \
        __syncthreads();                                                      \
        if ((IT) + 1 < SEQ / 64) {                                            \
            const int kt_ = ((IT) + 1) * 64;                                  \
            _Pragma("unroll")                                                 \
            for (int i_ = 0; i_ < 2; i_++) {                                  \
                cp16(kdst[(CUR) ^ 1] + i_ * (32*72*2),                        \
                     kb + (size_t)(kt_ + kr0 + i_ * 32) * HD + kq0);          \
                cp16(vdst[(CUR) ^ 1] + i_ * (32*72*2),                        \
                     vtb + (size_t)(vr0 + i_ * 32) * SEQ + kt_ + vq0);        \
            }                                                                 \
            CP_COMMIT();                                                      \
        }                                                                     \
        __half2 racc[2][2] = {{h2z, h2z}, {h2z, h2z}};                        \
        FLASH_HALF(CUR, 0)                                                    \
        FLASH_HALF(CUR, 32)                                                   \
        _Pragma("unroll")                                                     \
        for (int t = 0; t < 2; t++) {                                         \
            float2 f0 = __half22float2(racc[t][0]);                          \
            float2 f1 = __half22float2(racc[t][1]);                          \
            rs[t][0] += f0.x + f0.y;                                          \
            rs[t][1] += f1.x + f1.y;                                          \
        }                                                                     \
    }

__global__ __launch_bounds__(256, 2) void flash_kernel()
{
    extern __shared__ __half fsm[];
    __half (*Qs)[72]     = (__half(*)[72])(fsm);
    __half (*Ks)[64][72] = (__half(*)[64][72])(fsm + FLH_K);
    __half (*Vs)[64][72] = (__half(*)[64][72])(fsm + FLH_V);

    const int tid = threadIdx.x;
    const int lane = tid & 31;
    const int wid = tid >> 5;                 // 0..7
    const int gid = lane >> 2, tig = lane & 3;
    const int q0 = blockIdx.x * 256;
    const int bh = blockIdx.y;
    const __half2 h2z = __float2half2_rn(0.0f);

    const __half* qb  = g_q  + (size_t)bh * SEQ * HD + (size_t)q0 * HD;
    const __half* kb  = g_k  + (size_t)bh * SEQ * HD;
    const __half* vtb = g_vt + (size_t)bh * HD * SEQ;

    // prefetch geometry (loop-invariant): each thread covers rows r0 and r0+32
    const int kr0 = tid >> 3, kq0 = (tid & 7) * 8;   // K: [key][d], 64x64 halves
    const int vr0 = tid >> 3, vq0 = (tid & 7) * 8;   // V: [d][s],   64x64 halves
    const unsigned kdst[2] = { saddr(&Ks[0][kr0][kq0]), saddr(&Ks[1][kr0][kq0]) };
    const unsigned vdst[2] = { saddr(&Vs[0][vr0][vq0]), saddr(&Vs[1][vr0][vq0]) };

    // K/V tile 0 + Q tile -> smem (one cp.async group; 256 threads)
    {
        #pragma unroll
        for (int i = 0; i < 2; i++) {
            cp16(kdst[0] + i * (32*72*2), kb + (size_t)(kr0 + i * 32) * HD + kq0);
            cp16(vdst[0] + i * (32*72*2), vtb + (size_t)(vr0 + i * 32) * SEQ + vq0);
        }
        #pragma unroll
        for (int i = 0; i < 8; i++) {
            int c = tid + i * 256;
            int qr = c >> 3, qq = (c & 7) * 8;          // 256 x 64 halves
            cp16(saddr(&Qs[qr][qq]), qb + (size_t)qr * HD + qq);
        }
        CP_COMMIT();
    }
    CP_WAIT(0);
    __syncthreads();

    // Q fragments -> registers: 2 m-tiles x 4 k16-chunks per warp
    unsigned aq[2][4][4];
    #pragma unroll
    for (int t = 0; t < 2; t++)
        #pragma unroll
        for (int kk = 0; kk < 4; kk++)
            ldsm_x4(aq[t][kk][0], aq[t][kk][1], aq[t][kk][2], aq[t][kk][3],
                    saddr(&Qs[wid*32 + t*16 + (lane & 15)]
                             [kk*16 + ((lane >> 4) << 3)]));

    float O[2][8][4] = {};
    float rs[2][2] = {};

    for (int it = 0; it < SEQ / 64; it += 2) {
        FLASH_TILE(0, it)
        FLASH_TILE(1, it + 1)
    }

    // final row-sum reduction, writeback (fp16 feeds the out GEMM)
    const int b = bh >> 4, h = bh & 15;
    #pragma unroll
    for (int t = 0; t < 2; t++) {
        float r0 = rs[t][0], r1 = rs[t][1];
        r0 += __shfl_xor_sync(0xffffffffu, r0, 1);
        r0 += __shfl_xor_sync(0xffffffffu, r0, 2);
        r1 += __shfl_xor_sync(0xffffffffu, r1, 1);
        r1 += __shfl_xor_sync(0xffffffffu, r1, 2);
        const float inv0 = 1.0f / r0, inv1 = 1.0f / r1;
        const int s_lo = q0 + wid*32 + t*16 + gid;
        #pragma unroll
        for (int n = 0; n < 8; n++) {
            int d = h*64 + n*8 + 2*tig;
            *(__half2*)&g_ao[(size_t)(b*SEQ + s_lo    ) * DM + d] =
                __floats2half2_rn(O[t][n][0] * inv0, O[t][n][1] * inv0);
            *(__half2*)&g_ao[(size_t)(b*SEQ + s_lo + 8) * DM + d] =
                __floats2half2_rn(O[t][n][2] * inv1, O[t][n][3] * inv1);
        }
    }
}

// ---------------------------------------------------------------------------
extern "C" void kernel_launch(void* const* d_in, const int* in_sizes, int n_in,
                              void* d_out, int out_size)
{
    const float* x    = (const float*)d_in[0];
    const float* Wqkv = (const float*)d_in[1];
    const float* bqkv = (const float*)d_in[2];
    const float* Wout = (const float*)d_in[3];
    const float* bout = (const float*)d_in[4];
    float* out = (float*)d_out;

    cudaFuncSetAttribute(qkv_kernel,
                         cudaFuncAttributeMaxDynamicSharedMemorySize, GEMM_SMEM);
    cudaFuncSetAttribute(out_kernel,
                         cudaFuncAttributeMaxDynamicSharedMemorySize, GEMM_SMEM);
    cudaFuncSetAttribute(flash_kernel,
                         cudaFuncAttributeMaxDynamicSharedMemorySize, FL_SMEM);

    rope_init<<<SEQ * 32 / 256, 256>>>();
    tohalf_kernel<<<(NX8 + NWQ8 + NWO8) / 256, 256>>>(
        (const float4*)x, (const float4*)Wqkv, (const float4*)Wout);
    qkv_kernel<<<dim3(24, 64), 256, GEMM_SMEM>>>(bqkv);
    flash_kernel<<<dim3(SEQ / 256, 64), 256, FL_SMEM>>>();
    out_kernel<<<dim3(8, 64), 256, GEMM_SMEM>>>(bout, out);
}

// round 13
// speedup vs baseline: 1.3640x; 1.3640x over previous
#include <cuda_runtime.h>
#include <cuda_fp16.h>
#include <math.h>

#define BSZ 4
#define SEQ 2048
#define NH  16
#define HD  64
#define DM  1024
#define EXP_C 0.1803368801f   // 0.125 * log2(e), folded into q at the producer

// Scratch (device globals; no allocations allowed). All tensor operands fp16.
__device__ __half  g_x [BSZ*SEQ*DM];
__device__ __half  g_wq[3*DM*DM];
__device__ __half  g_wo[DM*DM];
__device__ __half  g_q [BSZ*NH*SEQ*HD];   // pre-scaled by EXP_C
__device__ __half  g_k [BSZ*NH*SEQ*HD];
__device__ __half  g_vt[BSZ*NH*HD*SEQ];   // V transposed: [bh][d][s]
__device__ __half  g_ao[BSZ*SEQ*DM];
__device__ float2  g_rope[SEQ*32];        // (cos,sin) per (pos, pair)

// ---------------------------------------------------------------------------
__device__ __forceinline__ float fast_ex2(float x) {
    float r; asm("ex2.approx.ftz.f32 %0, %1;" : "=f"(r) : "f"(x)); return r;
}
__device__ __forceinline__ unsigned packh2(float lo, float hi) {
    __half2 h = __floats2half2_rn(lo, hi);
    return *(unsigned*)&h;
}
__device__ __forceinline__ unsigned saddr(const void* p) {
    return (unsigned)__cvta_generic_to_shared(p);
}
__device__ __forceinline__ void cp16(unsigned d, const void* s) {
    asm volatile("cp.async.cg.shared.global [%0], [%1], 16;" :: "r"(d), "l"(s));
}
#define CP_COMMIT() asm volatile("cp.async.commit_group;")
#define CP_WAIT(n)  asm volatile("cp.async.wait_group %0;" :: "n"(n))

__device__ __forceinline__ void ldsm_x4(unsigned& r0, unsigned& r1,
                                        unsigned& r2, unsigned& r3, unsigned a) {
    asm volatile("ldmatrix.sync.aligned.m8n8.x4.shared.b16 {%0,%1,%2,%3}, [%4];"
                 : "=r"(r0), "=r"(r1), "=r"(r2), "=r"(r3) : "r"(a));
}
// fp16 mma, fp32 accumulate: D[16x8] += A[16x16] B[16x8]
__device__ __forceinline__ void mma_f16(float* c, const unsigned* a, const unsigned* b) {
    asm volatile("mma.sync.aligned.m16n8k16.row.col.f32.f16.f16.f32 "
                 "{%0,%1,%2,%3},{%4,%5,%6,%7},{%8,%9},{%0,%1,%2,%3};"
                 : "+f"(c[0]), "+f"(c[1]), "+f"(c[2]), "+f"(c[3])
                 : "r"(a[0]), "r"(a[1]), "r"(a[2]), "r"(a[3]), "r"(b[0]), "r"(b[1]));
}

// ---------------------------------------------------------------------------
__global__ void rope_init() {
    int i = blockIdx.x * 256 + threadIdx.x;   // SEQ*32 entries
    int m = i >> 5, p = i & 31;
    float theta = powf(10000.0f, -(float)p / 32.0f);
    float s, c; sincosf((float)m * theta, &s, &c);
    g_rope[i] = make_float2(c, s);
}

// Convert x / W_qkv / W_out to fp16 (RN). Unit of work: 8 elements.
#define NX8  (BSZ*SEQ*DM/8)
#define NWQ8 (3*DM*DM/8)
#define NWO8 (DM*DM/8)
__global__ __launch_bounds__(256) void tohalf_kernel(
    const float4* __restrict__ x, const float4* __restrict__ wq,
    const float4* __restrict__ wo)
{
    int i = blockIdx.x * 256 + threadIdx.x;
    const float4* src; __half* dst; int o;
    if (i < NX8)              { src = x;  dst = g_x;  o = i; }
    else if (i < NX8 + NWQ8)  { src = wq; dst = g_wq; o = i - NX8; }
    else                      { src = wo; dst = g_wo; o = i - NX8 - NWQ8; }
    float4 a = src[(size_t)o * 2], b = src[(size_t)o * 2 + 1];
    __half2 h[4];
    h[0] = __floats2half2_rn(a.x, a.y); h[1] = __floats2half2_rn(a.z, a.w);
    h[2] = __floats2half2_rn(b.x, b.y); h[3] = __floats2half2_rn(b.z, b.w);
    *(uint4*)(dst + (size_t)o * 8) = *(uint4*)h;
}

// ---------------------------------------------------------------------------
// GEMM core (fp16): C = A @ B^T, CTA tile 256x128 (8 warps 4x2, warp 64x64),
// k-chunk 64 (4 x k16 mma), 16 chunks, 3-stage cp.async, 1 barrier/chunk.
// smem: As[3][256][72] | Bs[3][128][72] halves = 165888 bytes (1 CTA/SM).
// ---------------------------------------------------------------------------
#define GEMM_SMEM ((3*256*72 + 3*128*72) * 2)

#define GEMM_PREFETCH(st, k0)                                                  \
    do {                                                                       \
        _Pragma("unroll")                                                      \
        for (int i_ = 0; i_ < 8; i_++) {                                       \
            int r_ = cr + i_ * 32;                                             \
            cp16(saddr(&As[st][r_][cq]), Abase + (size_t)r_ * DM + (k0) + cq); \
        }                                                                      \
        _Pragma("unroll")                                                      \
        for (int i_ = 0; i_ < 4; i_++) {                                       \
            int r_ = cr + i_ * 32;                                             \
            cp16(saddr(&Bs[st][r_][cq]), Bbase + (size_t)r_ * DM + (k0) + cq); \
        }                                                                      \
        CP_COMMIT();                                                           \
    } while (0)

#define GEMM_PIPELINE(AbaseE, BbaseE)                                          \
    const int lane = threadIdx.x & 31;                                         \
    const int wid  = threadIdx.x >> 5;                                         \
    const int wm = wid >> 1, wn = wid & 1;   /* 4 x 2 warp grid */             \
    extern __shared__ __half hsm[];                                            \
    __half (*As)[256][72] = (__half(*)[256][72])(hsm);                         \
    __half (*Bs)[128][72] = (__half(*)[128][72])(hsm + 3*256*72);              \
    float acc[4][8][4] = {};                                                   \
    const int cr = threadIdx.x >> 3;        /* 0..31 */                        \
    const int cq = (threadIdx.x & 7) * 8;   /* halves, 16B granule */          \
    const __half* Abase = (AbaseE);                                            \
    const __half* Bbase = (BbaseE);                                            \
    GEMM_PREFETCH(0, 0);                                                       \
    GEMM_PREFETCH(1, 64);                                                      \
    _Pragma("unroll")                                                          \
    for (int it = 0; it < 16; it++) {                                          \
        if (it + 2 < 16) { CP_WAIT(1); } else { CP_WAIT(0); }                  \
        __syncthreads();                                                       \
        if (it + 2 < 16) GEMM_PREFETCH((it + 2) % 3, (it + 2) * 64);           \
        const int cur = it % 3;                                                \
        _Pragma("unroll")                                                      \
        for (int kk = 0; kk < 4; kk++) {                                       \
            const int koff = kk*16 + ((lane >> 4) << 3);                       \
            unsigned a[4][4];                                                  \
            _Pragma("unroll")                                                  \
            for (int ma = 0; ma < 4; ma++)                                     \
                ldsm_x4(a[ma][0], a[ma][1], a[ma][2], a[ma][3],                \
                        saddr(&As[cur][wm*64 + ma*16 + (lane & 15)][koff]));   \
            unsigned b[8][2];                                                  \
            _Pragma("unroll")                                                  \
            for (int pr = 0; pr < 4; pr++) {                                   \
                unsigned r0, r1, r2, r3;                                       \
                ldsm_x4(r0, r1, r2, r3,                                        \
                        saddr(&Bs[cur][wn*64 + pr*16 + (lane & 15)][koff]));   \
                b[pr*2][0]   = r0; b[pr*2][1]   = r2;                          \
                b[pr*2+1][0] = r1; b[pr*2+1][1] = r3;                          \
            }                                                                  \
            _Pragma("unroll")                                                  \
            for (int ma = 0; ma < 4; ma++)                                     \
                _Pragma("unroll")                                              \
                for (int na = 0; na < 8; na++)                                 \
                    mma_f16(acc[ma][na], a[ma], b[na]);                        \
        }                                                                      \
    }

// ---------------------------------------------------------------------------
// QKV GEMM + bias + RoPE + scatter (fp16 outputs; V transposed).
// Q is additionally scaled by EXP_C so flash's exp is a bare ex2.
// ---------------------------------------------------------------------------
__global__ __launch_bounds__(256, 1) void qkv_kernel(const float* __restrict__ bias)
{
    const int m0 = blockIdx.y * 256;
    const int n0 = blockIdx.x * 128;

    GEMM_PIPELINE(g_x + (size_t)m0 * DM, g_wq + (size_t)n0 * DM)

    const int gid = lane >> 2, tig = lane & 3;
    const int which = n0 >> 10;                         // 0=q,1=k,2=v
    const int bq = m0 >> 11;
    const int s_base = (m0 & (SEQ-1)) + wm * 64;
    const int head = ((n0 & 1023) >> 6) + wn;           // warp covers 1 head
    const size_t bh = (size_t)(bq * NH + head);
    const float qscale = (which == 0) ? EXP_C : 1.0f;

    #pragma unroll
    for (int na = 0; na < 8; na++) {
        const int d = na*8 + 2*tig;                     // 0..63 within head
        const int ncol_g = n0 + wn*64 + d;
        const float b0v = bias[ncol_g], b1v = bias[ncol_g + 1];
        const int p = d >> 1;
        #pragma unroll
        for (int ma = 0; ma < 4; ma++) {
            int s_lo = s_base + ma*16 + gid;
            float v0 = acc[ma][na][0] + b0v;
            float v1 = acc[ma][na][1] + b1v;
            float u0 = acc[ma][na][2] + b0v;
            float u1 = acc[ma][na][3] + b1v;
            if (which == 2) {
                __half* vt = g_vt + bh * (size_t)(HD * SEQ);
                vt[(size_t)d     * SEQ + s_lo    ] = __float2half_rn(v0);
                vt[(size_t)(d+1) * SEQ + s_lo    ] = __float2half_rn(v1);
                vt[(size_t)d     * SEQ + s_lo + 8] = __float2half_rn(u0);
                vt[(size_t)(d+1) * SEQ + s_lo + 8] = __float2half_rn(u1);
            } else {
                __half* dst = (which == 0 ? g_q : g_k) + bh * (size_t)(SEQ * HD);
                float2 rl = g_rope[s_lo * 32 + p];
                float2 rh = g_rope[(s_lo + 8) * 32 + p];
                *(__half2*)&dst[(size_t)s_lo * HD + d] =
                    __floats2half2_rn((v0*rl.x - v1*rl.y) * qscale,
                                      (v1*rl.x + v0*rl.y) * qscale);
                *(__half2*)&dst[(size_t)(s_lo+8) * HD + d] =
                    __floats2half2_rn((u0*rh.x - u1*rh.y) * qscale,
                                      (u1*rh.x + u0*rh.y) * qscale);
            }
        }
    }
}

// ---------------------------------------------------------------------------
// Out-proj GEMM: out(fp32) = g_ao @ W_out^T + b_out
// ---------------------------------------------------------------------------
__global__ __launch_bounds__(256, 1) void out_kernel(
    const float* __restrict__ bias, float* __restrict__ out)
{
    const int m0 = blockIdx.y * 256;
    const int n0 = blockIdx.x * 128;

    GEMM_PIPELINE(g_ao + (size_t)m0 * DM, g_wo + (size_t)n0 * DM)

    const int gid = lane >> 2, tig = lane & 3;
    #pragma unroll
    for (int na = 0; na < 8; na++) {
        int col = n0 + wn*64 + na*8 + 2*tig;
        float b0v = bias[col], b1v = bias[col + 1];
        #pragma unroll
        for (int ma = 0; ma < 4; ma++) {
            int row = m0 + wm*64 + ma*16 + gid;
            out[(size_t)row       * DM + col    ] = acc[ma][na][0] + b0v;
            out[(size_t)row       * DM + col + 1] = acc[ma][na][1] + b1v;
            out[(size_t)(row + 8) * DM + col    ] = acc[ma][na][2] + b0v;
            out[(size_t)(row + 8) * DM + col + 1] = acc[ma][na][3] + b1v;
        }
    }
}

// ---------------------------------------------------------------------------
// Flash attention v7 (Round-11 best, fp32 ex2): 8 warps x 32 q-rows,
// Q + P fragments in registers, 64-key double-buffered K/V tiles, one barrier
// per 64 keys; q pre-scaled by EXP_C so exp is a bare fp32 ex2.
// smem halves: Qs[256][72] | Ks[2][64][72] | Vs[2][64][72]  = 73728 bytes
// ---------------------------------------------------------------------------
#define FLH_K  (256*72)
#define FLH_V  (FLH_K + 2*64*72)
#define FL_SMEM ((FLH_V + 2*64*72) * 2)   // 73728 bytes

// One 32-key half: keys H..H+31 of the CUR buffer.
#define FLASH_HALF(CUR, H)                                                    \
    {                                                                         \
        float S[2][4][4] = {};                                                \
        /* ---- S_A: keys H+0..H+15 ---- */                                   \
        _Pragma("unroll")                                                     \
        for (int kk = 0; kk < 4; kk++) {                                      \
            const int koff = kk*16 + ((lane >> 4) << 3);                      \
            unsigned r0, r1, r2, r3;                                          \
            ldsm_x4(r0, r1, r2, r3,                                           \
                    saddr(&Ks[CUR][(H) + (lane & 15)][koff]));                \
            unsigned b0[2] = {r0, r2}, b1[2] = {r1, r3};                      \
            _Pragma("unroll")                                                 \
            for (int t = 0; t < 2; t++) {                                     \
                mma_f16(S[t][0], aq[t][kk], b0);                              \
                mma_f16(S[t][1], aq[t][kk], b1);                              \
            }                                                                 \
        }                                                                     \
        /* ---- S_B: keys H+16..H+31 ---- */                                  \
        _Pragma("unroll")                                                     \
        for (int kk = 0; kk < 4; kk++) {                                      \
            const int koff = kk*16 + ((lane >> 4) << 3);                      \
            unsigned r0, r1, r2, r3;                                          \
            ldsm_x4(r0, r1, r2, r3,                                           \
                    saddr(&Ks[CUR][(H) + 16 + (lane & 15)][koff]));           \
            unsigned b0[2] = {r0, r2}, b1[2] = {r1, r3};                      \
            _Pragma("unroll")                                                 \
            for (int t = 0; t < 2; t++) {                                     \
                mma_f16(S[t][2], aq[t][kk], b0);                              \
                mma_f16(S[t][3], aq[t][kk], b1);                              \
            }                                                                 \
        }                                                                     \
        /* ---- exp_A: P (first 16 keys) -> PV A-fragments ---- */            \
        unsigned pa[2][4];                                                    \
        _Pragma("unroll")                                                     \
        for (int t = 0; t < 2; t++) {                                         \
            float p00 = fast_ex2(S[t][0][0]);                                 \
            float p01 = fast_ex2(S[t][0][1]);                                 \
            float p02 = fast_ex2(S[t][0][2]);                                 \
            float p03 = fast_ex2(S[t][0][3]);                                 \
            float p10 = fast_ex2(S[t][1][0]);                                 \
            float p11 = fast_ex2(S[t][1][1]);                                 \
            float p12 = fast_ex2(S[t][1][2]);                                 \
            float p13 = fast_ex2(S[t][1][3]);                                 \
            rs[t][0] += (p00 + p01) + (p10 + p11);                            \
            rs[t][1] += (p02 + p03) + (p12 + p13);                            \
            pa[t][0] = packh2(p00, p01);                                      \
            pa[t][1] = packh2(p02, p03);                                      \
            pa[t][2] = packh2(p10, p11);                                      \
            pa[t][3] = packh2(p12, p13);                                      \
        }                                                                     \
        /* ---- PV_A: V s-cols H..H+15 ---- */                                \
        {                                                                     \
            const int koff = (H) + ((lane >> 4) << 3);                        \
            _Pragma("unroll")                                                 \
            for (int pr = 0; pr < 4; pr++) {                                  \
                unsigned r0, r1, r2, r3;                                      \
                ldsm_x4(r0, r1, r2, r3,                                       \
                        saddr(&Vs[CUR][pr*16 + (lane & 15)][koff]));          \
                unsigned b0[2] = {r0, r2}, b1[2] = {r1, r3};                  \
                _Pragma("unroll")                                             \
                for (int t = 0; t < 2; t++) {                                 \
                    mma_f16(O[t][pr*2],   pa[t], b0);                         \
                    mma_f16(O[t][pr*2+1], pa[t], b1);                         \
                }                                                             \
            }                                                                 \
        }                                                                     \
        /* ---- exp_B: P (second 16 keys), overlaps PV_A ---- */              \
        unsigned pb[2][4];                                                    \
        _Pragma("unroll")                                                     \
        for (int t = 0; t < 2; t++) {                                         \
            float p00 = fast_ex2(S[t][2][0]);                                 \
            float p01 = fast_ex2(S[t][2][1]);                                 \
            float p02 = fast_ex2(S[t][2][2]);                                 \
            float p03 = fast_ex2(S[t][2][3]);                                 \
            float p10 = fast_ex2(S[t][3][0]);                                 \
            float p11 = fast_ex2(S[t][3][1]);                                 \
            float p12 = fast_ex2(S[t][3][2]);                                 \
            float p13 = fast_ex2(S[t][3][3]);                                 \
            rs[t][0] += (p00 + p01) + (p10 + p11);                            \
            rs[t][1] += (p02 + p03) + (p12 + p13);                            \
            pb[t][0] = packh2(p00, p01);                                      \
            pb[t][1] = packh2(p02, p03);                                      \
            pb[t][2] = packh2(p10, p11);                                      \
            pb[t][3] = packh2(p12, p13);                                      \
        }                                                                     \
        /* ---- PV_B: V s-cols H+16..H+31 ---- */                             \
        {                                                                     \
            const int koff = (H) + 16 + ((lane >> 4) << 3);                   \
            _Pragma("unroll")                                                 \
            for (int pr = 0; pr < 4; pr++) {                                  \
                unsigned r0, r1, r2, r3;                                      \
                ldsm_x4(r0, r1, r2, r3,                                       \
                        saddr(&Vs[CUR][pr*16 + (lane & 15)][koff]));          \
                unsigned b0[2] = {r0, r2}, b1[2] = {r1, r3};                  \
                _Pragma("unroll")                                             \
                for (int t = 0; t < 2; t++) {                                 \
                    mma_f16(O[t][pr*2],   pb[t], b0);                         \
                    mma_f16(O[t][pr*2+1], pb[t], b1);                         \
                }                                                             \
            }                                                                 \
        }                                                                     \
    }

// One 64-key tile: wait, prefetch next buffer, compute two halves.
#define FLASH_TILE(CUR, IT)                                                   \
    {                                                                         \
        CP_WAIT(0);                                                           \
        __syncthreads();                                                      \
        if ((IT) + 1 < SEQ / 64) {                                            \
            const int kt_ = ((IT) + 1) * 64;                                  \
            _Pragma("unroll")                                                 \
            for (int i_ = 0; i_ < 2; i_++) {                                  \
                cp16(kdst[(CUR) ^ 1] + i_ * (32*72*2),                        \
                     kb + (size_t)(kt_ + kr0 + i_ * 32) * HD + kq0);          \
                cp16(vdst[(CUR) ^ 1] + i_ * (32*72*2),                        \
                     vtb + (size_t)(vr0 + i_ * 32) * SEQ + kt_ + vq0);        \
            }                                                                 \
            CP_COMMIT();                                                      \
        }                                                                     \
        FLASH_HALF(CUR, 0)                                                    \
        FLASH_HALF(CUR, 32)                                                   \
    }

__global__ __launch_bounds__(256, 2) void flash_kernel()
{
    extern __shared__ __half fsm[];
    __half (*Qs)[72]     = (__half(*)[72])(fsm);
    __half (*Ks)[64][72] = (__half(*)[64][72])(fsm + FLH_K);
    __half (*Vs)[64][72] = (__half(*)[64][72])(fsm + FLH_V);

    const int tid = threadIdx.x;
    const int lane = tid & 31;
    const int wid = tid >> 5;                 // 0..7
    const int gid = lane >> 2, tig = lane & 3;
    const int q0 = blockIdx.x * 256;
    const int bh = blockIdx.y;

    const __half* qb  = g_q  + (size_t)bh * SEQ * HD + (size_t)q0 * HD;
    const __half* kb  = g_k  + (size_t)bh * SEQ * HD;
    const __half* vtb = g_vt + (size_t)bh * HD * SEQ;

    // prefetch geometry (loop-invariant): each thread covers rows r0 and r0+32
    const int kr0 = tid >> 3, kq0 = (tid & 7) * 8;   // K: [key][d], 64x64 halves
    const int vr0 = tid >> 3, vq0 = (tid & 7) * 8;   // V: [d][s],   64x64 halves
    const unsigned kdst[2] = { saddr(&Ks[0][kr0][kq0]), saddr(&Ks[1][kr0][kq0]) };
    const unsigned vdst[2] = { saddr(&Vs[0][vr0][vq0]), saddr(&Vs[1][vr0][vq0]) };

    // K/V tile 0 + Q tile -> smem (one cp.async group; 256 threads)
    {
        #pragma unroll
        for (int i = 0; i < 2; i++) {
            cp16(kdst[0] + i * (32*72*2), kb + (size_t)(kr0 + i * 32) * HD + kq0);
            cp16(vdst[0] + i * (32*72*2), vtb + (size_t)(vr0 + i * 32) * SEQ + vq0);
        }
        #pragma unroll
        for (int i = 0; i < 8; i++) {
            int c = tid + i * 256;
            int qr = c >> 3, qq = (c & 7) * 8;          // 256 x 64 halves
            cp16(saddr(&Qs[qr][qq]), qb + (size_t)qr * HD + qq);
        }
        CP_COMMIT();
    }
    CP_WAIT(0);
    __syncthreads();

    // Q fragments -> registers: 2 m-tiles x 4 k16-chunks per warp
    unsigned aq[2][4][4];
    #pragma unroll
    for (int t = 0; t < 2; t++)
        #pragma unroll
        for (int kk = 0; kk < 4; kk++)
            ldsm_x4(aq[t][kk][0], aq[t][kk][1], aq[t][kk][2], aq[t][kk][3],
                    saddr(&Qs[wid*32 + t*16 + (lane & 15)]
                             [kk*16 + ((lane >> 4) << 3)]));

    float O[2][8][4] = {};
    float rs[2][2] = {};

    for (int it = 0; it < SEQ / 64; it += 2) {
        FLASH_TILE(0, it)
        FLASH_TILE(1, it + 1)
    }

    // final row-sum reduction, writeback (fp16 feeds the out GEMM)
    const int b = bh >> 4, h = bh & 15;
    #pragma unroll
    for (int t = 0; t < 2; t++) {
        float r0 = rs[t][0], r1 = rs[t][1];
        r0 += __shfl_xor_sync(0xffffffffu, r0, 1);
        r0 += __shfl_xor_sync(0xffffffffu, r0, 2);
        r1 += __shfl_xor_sync(0xffffffffu, r1, 1);
        r1 += __shfl_xor_sync(0xffffffffu, r1, 2);
        const float inv0 = 1.0f / r0, inv1 = 1.0f / r1;
        const int s_lo = q0 + wid*32 + t*16 + gid;
        #pragma unroll
        for (int n = 0; n < 8; n++) {
            int d = h*64 + n*8 + 2*tig;
            *(__half2*)&g_ao[(size_t)(b*SEQ + s_lo    ) * DM + d] =
                __floats2half2_rn(O[t][n][0] * inv0, O[t][n][1] * inv0);
            *(__half2*)&g_ao[(size_t)(b*SEQ + s_lo + 8) * DM + d] =
                __floats2half2_rn(O[t][n][2] * inv1, O[t][n][3] * inv1);
        }
    }
}

// ---------------------------------------------------------------------------
extern "C" void kernel_launch(void* const* d_in, const int* in_sizes, int n_in,
                              void* d_out, int out_size)
{
    const float* x    = (const float*)d_in[0];
    const float* Wqkv = (const float*)d_in[1];
    const float* bqkv = (const float*)d_in[2];
    const float* Wout = (const float*)d_in[3];
    const float* bout = (const float*)d_in[4];
    float* out = (float*)d_out;

    cudaFuncSetAttribute(qkv_kernel,
                         cudaFuncAttributeMaxDynamicSharedMemorySize, GEMM_SMEM);
    cudaFuncSetAttribute(out_kernel,
                         cudaFuncAttributeMaxDynamicSharedMemorySize, GEMM_SMEM);
    cudaFuncSetAttribute(flash_kernel,
                         cudaFuncAttributeMaxDynamicSharedMemorySize, FL_SMEM);

    rope_init<<<SEQ * 32 / 256, 256>>>();
    tohalf_kernel<<<(NX8 + NWQ8 + NWO8) / 256, 256>>>(
        (const float4*)x, (const float4*)Wqkv, (const float4*)Wout);
    qkv_kernel<<<dim3(24, 32), 256, GEMM_SMEM>>>(bqkv);
    flash_kernel<<<dim3(SEQ / 256, 64), 256, FL_SMEM>>>();
    out_kernel<<<dim3(8, 32), 256, GEMM_SMEM>>>(bout, out);
}

// round 14
// speedup vs baseline: 1.4913x; 1.0933x over previous
#include <cuda_runtime.h>
#include <cuda_fp16.h>
#include <math.h>

#define BSZ 4
#define SEQ 2048
#define NH  16
#define HD  64
#define DM  1024
#define EXP_C 0.1803368801f   // 0.125 * log2(e), folded into q at the producer

// Scratch (device globals; no allocations allowed). All tensor operands fp16.
__device__ __half  g_x [BSZ*SEQ*DM];
__device__ __half  g_wq[3*DM*DM];
__device__ __half  g_wo[DM*DM];
__device__ __half  g_q [BSZ*NH*SEQ*HD];   // pre-scaled by EXP_C
__device__ __half  g_k [BSZ*NH*SEQ*HD];
__device__ __half  g_vt[BSZ*NH*HD*SEQ];   // V transposed: [bh][d][s]
__device__ __half  g_ao[BSZ*SEQ*DM];
__device__ float2  g_rope[SEQ*32];        // (cos,sin) per (pos, pair)

// ---------------------------------------------------------------------------
__device__ __forceinline__ float fast_ex2(float x) {
    float r; asm("ex2.approx.ftz.f32 %0, %1;" : "=f"(r) : "f"(x)); return r;
}
__device__ __forceinline__ unsigned packh2(float lo, float hi) {
    __half2 h = __floats2half2_rn(lo, hi);
    return *(unsigned*)&h;
}
__device__ __forceinline__ unsigned saddr(const void* p) {
    return (unsigned)__cvta_generic_to_shared(p);
}
__device__ __forceinline__ void cp16(unsigned d, const void* s) {
    asm volatile("cp.async.cg.shared.global [%0], [%1], 16;" :: "r"(d), "l"(s));
}
#define CP_COMMIT() asm volatile("cp.async.commit_group;")
#define CP_WAIT(n)  asm volatile("cp.async.wait_group %0;" :: "n"(n))

__device__ __forceinline__ void ldsm_x4(unsigned& r0, unsigned& r1,
                                        unsigned& r2, unsigned& r3, unsigned a) {
    asm volatile("ldmatrix.sync.aligned.m8n8.x4.shared.b16 {%0,%1,%2,%3}, [%4];"
                 : "=r"(r0), "=r"(r1), "=r"(r2), "=r"(r3) : "r"(a));
}
// fp16 mma, fp32 accumulate: D[16x8] += A[16x16] B[16x8]
__device__ __forceinline__ void mma_f16(float* c, const unsigned* a, const unsigned* b) {
    asm volatile("mma.sync.aligned.m16n8k16.row.col.f32.f16.f16.f32 "
                 "{%0,%1,%2,%3},{%4,%5,%6,%7},{%8,%9},{%0,%1,%2,%3};"
                 : "+f"(c[0]), "+f"(c[1]), "+f"(c[2]), "+f"(c[3])
                 : "r"(a[0]), "r"(a[1]), "r"(a[2]), "r"(a[3]), "r"(b[0]), "r"(b[1]));
}

// ---------------------------------------------------------------------------
// Init: rope table + fp16 conversion of x / W_qkv / W_out, one kernel.
// ---------------------------------------------------------------------------
#define NX8  (BSZ*SEQ*DM/8)
#define NWQ8 (3*DM*DM/8)
#define NWO8 (DM*DM/8)
#define ROPE_BLOCKS (SEQ*32/256)                       // 256
#define INIT_BLOCKS (ROPE_BLOCKS + (NX8+NWQ8+NWO8)/256)

__global__ __launch_bounds__(256) void init_kernel(
    const float4* __restrict__ x, const float4* __restrict__ wq,
    const float4* __restrict__ wo)
{
    int bid = blockIdx.x;
    if (bid < ROPE_BLOCKS) {
        int i = bid * 256 + threadIdx.x;               // SEQ*32 entries
        int m = i >> 5, p = i & 31;
        float theta = powf(10000.0f, -(float)p / 32.0f);
        float s, c; sincosf((float)m * theta, &s, &c);
        g_rope[i] = make_float2(c, s);
        return;
    }
    int i = (bid - ROPE_BLOCKS) * 256 + threadIdx.x;
    const float4* src; __half* dst; int o;
    if (i < NX8)              { src = x;  dst = g_x;  o = i; }
    else if (i < NX8 + NWQ8)  { src = wq; dst = g_wq; o = i - NX8; }
    else                      { src = wo; dst = g_wo; o = i - NX8 - NWQ8; }
    float4 a = src[(size_t)o * 2], b = src[(size_t)o * 2 + 1];
    __half2 h[4];
    h[0] = __floats2half2_rn(a.x, a.y); h[1] = __floats2half2_rn(a.z, a.w);
    h[2] = __floats2half2_rn(b.x, b.y); h[3] = __floats2half2_rn(b.z, b.w);
    *(uint4*)(dst + (size_t)o * 8) = *(uint4*)h;
}

// ---------------------------------------------------------------------------
// GEMM core (fp16, Round-11 config): C = A @ B^T, CTA tile 128x128,
// k-chunk 64 (4 x k16 mma), 16 chunks fully unrolled, 3-stage cp.async,
// one barrier per chunk. 8 warps (2x4), warp tile 64x32.
// ---------------------------------------------------------------------------
#define GEMM_SMEM (6*128*72*2)

#define GEMM_PREFETCH(st, k0)                                                  \
    do {                                                                       \
        _Pragma("unroll")                                                      \
        for (int i_ = 0; i_ < 4; i_++) {                                       \
            int r_ = cr + i_ * 32;                                             \
            cp16(saddr(&As[st][r_][cq]), Abase + (size_t)r_ * DM + (k0) + cq); \
            cp16(saddr(&Bs[st][r_][cq]), Bbase + (size_t)r_ * DM + (k0) + cq); \
        }                                                                      \
        CP_COMMIT();                                                           \
    } while (0)

#define GEMM_PIPELINE(AbaseE, BbaseE)                                          \
    const int lane = threadIdx.x & 31;                                         \
    const int wid  = threadIdx.x >> 5;                                         \
    const int wm = wid >> 2, wn = wid & 3;                                     \
    extern __shared__ __half hsm[];                                            \
    __half (*As)[128][72] = (__half(*)[128][72])(hsm);                         \
    __half (*Bs)[128][72] = (__half(*)[128][72])(hsm + 3*128*72);              \
    float acc[4][4][4] = {};                                                   \
    const int cr = threadIdx.x >> 3;        /* 0..31 */                        \
    const int cq = (threadIdx.x & 7) * 8;   /* halves, 16B granule */          \
    const __half* Abase = (AbaseE);                                            \
    const __half* Bbase = (BbaseE);                                            \
    GEMM_PREFETCH(0, 0);                                                       \
    GEMM_PREFETCH(1, 64);                                                      \
    _Pragma("unroll")                                                          \
    for (int it = 0; it < 16; it++) {                                          \
        if (it + 2 < 16) { CP_WAIT(1); } else { CP_WAIT(0); }                  \
        __syncthreads();                                                       \
        if (it + 2 < 16) GEMM_PREFETCH((it + 2) % 3, (it + 2) * 64);           \
        const int cur = it % 3;                                                \
        _Pragma("unroll")                                                      \
        for (int kk = 0; kk < 4; kk++) {                                       \
            const int koff = kk*16 + ((lane >> 4) << 3);                       \
            unsigned a[4][4];                                                  \
            _Pragma("unroll")                                                  \
            for (int ma = 0; ma < 4; ma++)                                     \
                ldsm_x4(a[ma][0], a[ma][1], a[ma][2], a[ma][3],                \
                        saddr(&As[cur][wm*64 + ma*16 + (lane & 15)][koff]));   \
            unsigned b[4][2];                                                  \
            _Pragma("unroll")                                                  \
            for (int pr = 0; pr < 2; pr++) {                                   \
                unsigned r0, r1, r2, r3;                                       \
                ldsm_x4(r0, r1, r2, r3,                                        \
                        saddr(&Bs[cur][wn*32 + pr*16 + (lane & 15)][koff]));   \
                b[pr*2][0]   = r0; b[pr*2][1]   = r2;                          \
                b[pr*2+1][0] = r1; b[pr*2+1][1] = r3;                          \
            }                                                                  \
            _Pragma("unroll")                                                  \
            for (int ma = 0; ma < 4; ma++)                                     \
                _Pragma("unroll")                                              \
                for (int na = 0; na < 4; na++)                                 \
                    mma_f16(acc[ma][na], a[ma], b[na]);                        \
        }                                                                      \
    }

// ---------------------------------------------------------------------------
// QKV GEMM + bias + RoPE + scatter (fp16 outputs; V transposed).
// Q is additionally scaled by EXP_C so flash's exp is a bare ex2.
// ---------------------------------------------------------------------------
__global__ __launch_bounds__(256, 2) void qkv_kernel(const float* __restrict__ bias)
{
    const int m0 = blockIdx.y * 128;
    const int n0 = blockIdx.x * 128;

    GEMM_PIPELINE(g_x + (size_t)m0 * DM, g_wq + (size_t)n0 * DM)

    const int gid = lane >> 2, tig = lane & 3;
    const int which = n0 >> 10;                         // 0=q,1=k,2=v
    const int bq = m0 >> 11;
    const int s_base = (m0 & (SEQ-1)) + wm * 64;
    const int col_local = (n0 & 1023) + wn * 32;
    const int head = col_local >> 6;
    const int d0 = col_local & 63;
    const size_t bh = (size_t)(bq * NH + head);
    const float qscale = (which == 0) ? EXP_C : 1.0f;

    #pragma unroll
    for (int na = 0; na < 4; na++) {
        const int d = d0 + na*8 + 2*tig;
        const int ncol_g = n0 + wn*32 + na*8 + 2*tig;
        const float b0v = bias[ncol_g], b1v = bias[ncol_g + 1];
        const int p = d >> 1;
        #pragma unroll
        for (int ma = 0; ma < 4; ma++) {
            int s_lo = s_base + ma*16 + gid;
            float v0 = acc[ma][na][0] + b0v;
            float v1 = acc[ma][na][1] + b1v;
            float u0 = acc[ma][na][2] + b0v;
            float u1 = acc[ma][na][3] + b1v;
            if (which == 2) {
                __half* vt = g_vt + bh * (size_t)(HD * SEQ);
                vt[(size_t)d     * SEQ + s_lo    ] = __float2half_rn(v0);
                vt[(size_t)(d+1) * SEQ + s_lo    ] = __float2half_rn(v1);
                vt[(size_t)d     * SEQ + s_lo + 8] = __float2half_rn(u0);
                vt[(size_t)(d+1) * SEQ + s_lo + 8] = __float2half_rn(u1);
            } else {
                __half* dst = (which == 0 ? g_q : g_k) + bh * (size_t)(SEQ * HD);
                float2 rl = g_rope[s_lo * 32 + p];
                float2 rh = g_rope[(s_lo + 8) * 32 + p];
                *(__half2*)&dst[(size_t)s_lo * HD + d] =
                    __floats2half2_rn((v0*rl.x - v1*rl.y) * qscale,
                                      (v1*rl.x + v0*rl.y) * qscale);
                *(__half2*)&dst[(size_t)(s_lo+8) * HD + d] =
                    __floats2half2_rn((u0*rh.x - u1*rh.y) * qscale,
                                      (u1*rh.x + u0*rh.y) * qscale);
            }
        }
    }
}

// ---------------------------------------------------------------------------
// Out-proj GEMM: out(fp32) = g_ao @ W_out^T + b_out
// ---------------------------------------------------------------------------
__global__ __launch_bounds__(256, 2) void out_kernel(
    const float* __restrict__ bias, float* __restrict__ out)
{
    const int m0 = blockIdx.y * 128;
    const int n0 = blockIdx.x * 128;

    GEMM_PIPELINE(g_ao + (size_t)m0 * DM, g_wo + (size_t)n0 * DM)

    const int gid = lane >> 2, tig = lane & 3;
    #pragma unroll
    for (int na = 0; na < 4; na++) {
        int col = n0 + wn*32 + na*8 + 2*tig;
        float b0v = bias[col], b1v = bias[col + 1];
        #pragma unroll
        for (int ma = 0; ma < 4; ma++) {
            int row = m0 + wm*64 + ma*16 + gid;
            out[(size_t)row       * DM + col    ] = acc[ma][na][0] + b0v;
            out[(size_t)row       * DM + col + 1] = acc[ma][na][1] + b1v;
            out[(size_t)(row + 8) * DM + col    ] = acc[ma][na][2] + b0v;
            out[(size_t)(row + 8) * DM + col + 1] = acc[ma][na][3] + b1v;
        }
    }
}

// ---------------------------------------------------------------------------
// Flash attention v9: Round-11 compute structure (fp32 ex2, register P),
// with TRIPLE-buffered 64-key K/V tiles: prefetch distance 2 tiles, so each
// cp.async has ~2 tiles of compute to cover DRAM latency; CP_WAIT(1) keeps
// one group in flight at every wait.
// smem halves: Qs[256][72] | Ks[3][64][72] | Vs[3][64][72]  = 92160 bytes
// ---------------------------------------------------------------------------
#define FLH_K  (256*72)
#define FLH_V  (FLH_K + 3*64*72)
#define FL_SMEM ((FLH_V + 3*64*72) * 2)   // 92160 bytes
#define NT     (SEQ/64)                    // 32 tiles

// One 32-key half: keys H..H+31 of the CUR buffer.
#define FLASH_HALF(CUR, H)                                                    \
    {                                                                         \
        float S[2][4][4] = {};                                                \
        /* ---- S_A: keys H+0..H+15 ---- */                                   \
        _Pragma("unroll")                                                     \
        for (int kk = 0; kk < 4; kk++) {                                      \
            const int koff = kk*16 + ((lane >> 4) << 3);                      \
            unsigned r0, r1, r2, r3;                                          \
            ldsm_x4(r0, r1, r2, r3,                                           \
                    saddr(&Ks[CUR][(H) + (lane & 15)][koff]));                \
            unsigned b0[2] = {r0, r2}, b1[2] = {r1, r3};                      \
            _Pragma("unroll")                                                 \
            for (int t = 0; t < 2; t++) {                                     \
                mma_f16(S[t][0], aq[t][kk], b0);                              \
                mma_f16(S[t][1], aq[t][kk], b1);                              \
            }                                                                 \
        }                                                                     \
        /* ---- S_B: keys H+16..H+31 ---- */                                  \
        _Pragma("unroll")                                                     \
        for (int kk = 0; kk < 4; kk++) {                                      \
            const int koff = kk*16 + ((lane >> 4) << 3);                      \
            unsigned r0, r1, r2, r3;                                          \
            ldsm_x4(r0, r1, r2, r3,                                           \
                    saddr(&Ks[CUR][(H) + 16 + (lane & 15)][koff]));           \
            unsigned b0[2] = {r0, r2}, b1[2] = {r1, r3};                      \
            _Pragma("unroll")                                                 \
            for (int t = 0; t < 2; t++) {                                     \
                mma_f16(S[t][2], aq[t][kk], b0);                              \
                mma_f16(S[t][3], aq[t][kk], b1);                              \
            }                                                                 \
        }                                                                     \
        /* ---- exp_A: P (first 16 keys) -> PV A-fragments ---- */            \
        unsigned pa[2][4];                                                    \
        _Pragma("unroll")                                                     \
        for (int t = 0; t < 2; t++) {                                         \
            float p00 = fast_ex2(S[t][0][0]);                                 \
            float p01 = fast_ex2(S[t][0][1]);                                 \
            float p02 = fast_ex2(S[t][0][2]);                                 \
            float p03 = fast_ex2(S[t][0][3]);                                 \
            float p10 = fast_ex2(S[t][1][0]);                                 \
            float p11 = fast_ex2(S[t][1][1]);                                 \
            float p12 = fast_ex2(S[t][1][2]);                                 \
            float p13 = fast_ex2(S[t][1][3]);                                 \
            rs[t][0] += (p00 + p01) + (p10 + p11);                            \
            rs[t][1] += (p02 + p03) + (p12 + p13);                            \
            pa[t][0] = packh2(p00, p01);                                      \
            pa[t][1] = packh2(p02, p03);                                      \
            pa[t][2] = packh2(p10, p11);                                      \
            pa[t][3] = packh2(p12, p13);                                      \
        }                                                                     \
        /* ---- PV_A: V s-cols H..H+15 ---- */                                \
        {                                                                     \
            const int koff = (H) + ((lane >> 4) << 3);                        \
            _Pragma("unroll")                                                 \
            for (int pr = 0; pr < 4; pr++) {                                  \
                unsigned r0, r1, r2, r3;                                      \
                ldsm_x4(r0, r1, r2, r3,                                       \
                        saddr(&Vs[CUR][pr*16 + (lane & 15)][koff]));          \
                unsigned b0[2] = {r0, r2}, b1[2] = {r1, r3};                  \
                _Pragma("unroll")                                             \
                for (int t = 0; t < 2; t++) {                                 \
                    mma_f16(O[t][pr*2],   pa[t], b0);                         \
                    mma_f16(O[t][pr*2+1], pa[t], b1);                         \
                }                                                             \
            }                                                                 \
        }                                                                     \
        /* ---- exp_B: P (second 16 keys), overlaps PV_A ---- */              \
        unsigned pb[2][4];                                                    \
        _Pragma("unroll")                                                     \
        for (int t = 0; t < 2; t++) {                                         \
            float p00 = fast_ex2(S[t][2][0]);                                 \
            float p01 = fast_ex2(S[t][2][1]);                                 \
            float p02 = fast_ex2(S[t][2][2]);                                 \
            float p03 = fast_ex2(S[t][2][3]);                                 \
            float p10 = fast_ex2(S[t][3][0]);                                 \
            float p11 = fast_ex2(S[t][3][1]);                                 \
            float p12 = fast_ex2(S[t][3][2]);                                 \
            float p13 = fast_ex2(S[t][3][3]);                                 \
            rs[t][0] += (p00 + p01) + (p10 + p11);                            \
            rs[t][1] += (p02 + p03) + (p12 + p13);                            \
            pb[t][0] = packh2(p00, p01);                                      \
            pb[t][1] = packh2(p02, p03);                                      \
            pb[t][2] = packh2(p10, p11);                                      \
            pb[t][3] = packh2(p12, p13);                                      \
        }                                                                     \
        /* ---- PV_B: V s-cols H+16..H+31 ---- */                             \
        {                                                                     \
            const int koff = (H) + 16 + ((lane >> 4) << 3);                   \
            _Pragma("unroll")                                                 \
            for (int pr = 0; pr < 4; pr++) {                                  \
                unsigned r0, r1, r2, r3;                                      \
                ldsm_x4(r0, r1, r2, r3,                                       \
                        saddr(&Vs[CUR][pr*16 + (lane & 15)][koff]));          \
                unsigned b0[2] = {r0, r2}, b1[2] = {r1, r3};                  \
                _Pragma("unroll")                                             \
                for (int t = 0; t < 2; t++) {                                 \
                    mma_f16(O[t][pr*2],   pb[t], b0);                         \
                    mma_f16(O[t][pr*2+1], pb[t], b1);                         \
                }                                                             \
            }                                                                 \
        }                                                                     \
    }

// One 64-key tile. NXT = (CUR+2)%3 (compile-time). Prefetch distance = 2.
#define FLASH_TILE(CUR, NXT, IT)                                              \
    {                                                                         \
        if ((IT) + 1 < NT) { CP_WAIT(1); } else { CP_WAIT(0); }               \
        __syncthreads();                                                      \
        if ((IT) + 2 < NT) {                                                  \
            const int kt_ = ((IT) + 2) * 64;                                  \
            _Pragma("unroll")                                                 \
            for (int i_ = 0; i_ < 2; i_++) {                                  \
                cp16(kdst[NXT] + i_ * (32*72*2),                              \
                     kb + (size_t)(kt_ + kr0 + i_ * 32) * HD + kq0);          \
                cp16(vdst[NXT] + i_ * (32*72*2),                              \
                     vtb + (size_t)(vr0 + i_ * 32) * SEQ + kt_ + vq0);        \
            }                                                                 \
            CP_COMMIT();                                                      \
        }                                                                     \
        FLASH_HALF(CUR, 0)                                                    \
        FLASH_HALF(CUR, 32)                                                   \
    }

__global__ __launch_bounds__(256, 2) void flash_kernel()
{
    extern __shared__ __half fsm[];
    __half (*Qs)[72]     = (__half(*)[72])(fsm);
    __half (*Ks)[64][72] = (__half(*)[64][72])(fsm + FLH_K);
    __half (*Vs)[64][72] = (__half(*)[64][72])(fsm + FLH_V);

    const int tid = threadIdx.x;
    const int lane = tid & 31;
    const int wid = tid >> 5;                 // 0..7
    const int gid = lane >> 2, tig = lane & 3;
    const int q0 = blockIdx.x * 256;
    const int bh = blockIdx.y;

    const __half* qb  = g_q  + (size_t)bh * SEQ * HD + (size_t)q0 * HD;
    const __half* kb  = g_k  + (size_t)bh * SEQ * HD;
    const __half* vtb = g_vt + (size_t)bh * HD * SEQ;

    // prefetch geometry (loop-invariant): each thread covers rows r0 and r0+32
    const int kr0 = tid >> 3, kq0 = (tid & 7) * 8;   // K: [key][d], 64x64 halves
    const int vr0 = tid >> 3, vq0 = (tid & 7) * 8;   // V: [d][s],   64x64 halves
    const unsigned kdst[3] = { saddr(&Ks[0][kr0][kq0]), saddr(&Ks[1][kr0][kq0]),
                               saddr(&Ks[2][kr0][kq0]) };
    const unsigned vdst[3] = { saddr(&Vs[0][vr0][vq0]), saddr(&Vs[1][vr0][vq0]),
                               saddr(&Vs[2][vr0][vq0]) };

    // Group 1: K/V tile 0 + Q tile. Group 2: K/V tile 1.
    {
        #pragma unroll
        for (int i = 0; i < 2; i++) {
            cp16(kdst[0] + i * (32*72*2), kb + (size_t)(kr0 + i * 32) * HD + kq0);
            cp16(vdst[0] + i * (32*72*2), vtb + (size_t)(vr0 + i * 32) * SEQ + vq0);
        }
        #pragma unroll
        for (int i = 0; i < 8; i++) {
            int c = tid + i * 256;
            int qr = c >> 3, qq = (c & 7) * 8;          // 256 x 64 halves
            cp16(saddr(&Qs[qr][qq]), qb + (size_t)qr * HD + qq);
        }
        CP_COMMIT();
        #pragma unroll
        for (int i = 0; i < 2; i++) {
            cp16(kdst[1] + i * (32*72*2), kb + (size_t)(64 + kr0 + i * 32) * HD + kq0);
            cp16(vdst[1] + i * (32*72*2), vtb + (size_t)(vr0 + i * 32) * SEQ + 64 + vq0);
        }
        CP_COMMIT();
    }
    CP_WAIT(1);       // Q + tile 0 ready; tile 1 in flight
    __syncthreads();

    // Q fragments -> registers: 2 m-tiles x 4 k16-chunks per warp
    unsigned aq[2][4][4];
    #pragma unroll
    for (int t = 0; t < 2; t++)
        #pragma unroll
        for (int kk = 0; kk < 4; kk++)
            ldsm_x4(aq[t][kk][0], aq[t][kk][1], aq[t][kk][2], aq[t][kk][3],
                    saddr(&Qs[wid*32 + t*16 + (lane & 15)]
                             [kk*16 + ((lane >> 4) << 3)]));

    float O[2][8][4] = {};
    float rs[2][2] = {};

    // 32 tiles = 10 x 3 + 2 tail; tile j lives in buffer j%3 throughout.
    int it = 0;
    for (; it + 2 < NT; it += 3) {
        FLASH_TILE(0, 2, it)
        FLASH_TILE(1, 0, it + 1)
        FLASH_TILE(2, 1, it + 2)
    }
    FLASH_TILE(0, 2, it)        // tile 30 (buf 0)
    FLASH_TILE(1, 0, it + 1)    // tile 31 (buf 1)

    // final row-sum reduction, writeback (fp16 feeds the out GEMM)
    const int b = bh >> 4, h = bh & 15;
    #pragma unroll
    for (int t = 0; t < 2; t++) {
        float r0 = rs[t][0], r1 = rs[t][1];
        r0 += __shfl_xor_sync(0xffffffffu, r0, 1);
        r0 += __shfl_xor_sync(0xffffffffu, r0, 2);
        r1 += __shfl_xor_sync(0xffffffffu, r1, 1);
        r1 += __shfl_xor_sync(0xffffffffu, r1, 2);
        const float inv0 = 1.0f / r0, inv1 = 1.0f / r1;
        const int s_lo = q0 + wid*32 + t*16 + gid;
        #pragma unroll
        for (int n = 0; n < 8; n++) {
            int d = h*64 + n*8 + 2*tig;
            *(__half2*)&g_ao[(size_t)(b*SEQ + s_lo    ) * DM + d] =
                __floats2half2_rn(O[t][n][0] * inv0, O[t][n][1] * inv0);
            *(__half2*)&g_ao[(size_t)(b*SEQ + s_lo + 8) * DM + d] =
                __floats2half2_rn(O[t][n][2] * inv1, O[t][n][3] * inv1);
        }
    }
}

// ---------------------------------------------------------------------------
extern "C" void kernel_launch(void* const* d_in, const int* in_sizes, int n_in,
                              void* d_out, int out_size)
{
    const float* x    = (const float*)d_in[0];
    const float* Wqkv = (const float*)d_in[1];
    const float* bqkv = (const float*)d_in[2];
    const float* Wout = (const float*)d_in[3];
    const float* bout = (const float*)d_in[4];
    float* out = (float*)d_out;

    cudaFuncSetAttribute(qkv_kernel,
                         cudaFuncAttributeMaxDynamicSharedMemorySize, GEMM_SMEM);
    cudaFuncSetAttribute(out_kernel,
                         cudaFuncAttributeMaxDynamicSharedMemorySize, GEMM_SMEM);
    cudaFuncSetAttribute(flash_kernel,
                         cudaFuncAttributeMaxDynamicSharedMemorySize, FL_SMEM);

    init_kernel<<<INIT_BLOCKS, 256>>>(
        (const float4*)x, (const float4*)Wqkv, (const float4*)Wout);
    qkv_kernel<<<dim3(24, 64), 256, GEMM_SMEM>>>(bqkv);
    flash_kernel<<<dim3(SEQ / 256, 64), 256, FL_SMEM>>>();
    out_kernel<<<dim3(8, 64), 256, GEMM_SMEM>>>(bout, out);
}

// round 15
// speedup vs baseline: 1.5345x; 1.0290x over previous
#include <cuda_runtime.h>
#include <cuda_fp16.h>
#include <math.h>

#define BSZ 4
#define SEQ 2048
#define NH  16
#define HD  64
#define DM  1024
#define EXP_C 0.1803368801f   // 0.125 * log2(e), folded into q at the producer

// Scratch (device globals; no allocations allowed). All tensor operands fp16.
__device__ __half  g_x [BSZ*SEQ*DM];
__device__ __half  g_wq[3*DM*DM];
__device__ __half  g_wo[DM*DM];
__device__ __half  g_q [BSZ*NH*SEQ*HD];   // pre-scaled by EXP_C
__device__ __half  g_k [BSZ*NH*SEQ*HD];
__device__ __half  g_vt[BSZ*NH*HD*SEQ];   // V transposed: [bh][d][s]
__device__ __half  g_ao[BSZ*SEQ*DM];
__device__ float2  g_rope[SEQ*32];        // (cos,sin) per (pos, pair)

// ---------------------------------------------------------------------------
__device__ __forceinline__ float fast_ex2(float x) {
    float r; asm("ex2.approx.ftz.f32 %0, %1;" : "=f"(r) : "f"(x)); return r;
}
__device__ __forceinline__ unsigned packh2(float lo, float hi) {
    __half2 h = __floats2half2_rn(lo, hi);
    return *(unsigned*)&h;
}
__device__ __forceinline__ unsigned saddr(const void* p) {
    return (unsigned)__cvta_generic_to_shared(p);
}
__device__ __forceinline__ void cp16(unsigned d, const void* s) {
    asm volatile("cp.async.cg.shared.global [%0], [%1], 16;" :: "r"(d), "l"(s));
}
#define CP_COMMIT() asm volatile("cp.async.commit_group;")
#define CP_WAIT(n)  asm volatile("cp.async.wait_group %0;" :: "n"(n))

__device__ __forceinline__ void ldsm_x4(unsigned& r0, unsigned& r1,
                                        unsigned& r2, unsigned& r3, unsigned a) {
    asm volatile("ldmatrix.sync.aligned.m8n8.x4.shared.b16 {%0,%1,%2,%3}, [%4];"
                 : "=r"(r0), "=r"(r1), "=r"(r2), "=r"(r3) : "r"(a));
}
// fp16 mma, fp32 accumulate: D[16x8] += A[16x16] B[16x8]
__device__ __forceinline__ void mma_f16(float* c, const unsigned* a, const unsigned* b) {
    asm volatile("mma.sync.aligned.m16n8k16.row.col.f32.f16.f16.f32 "
                 "{%0,%1,%2,%3},{%4,%5,%6,%7},{%8,%9},{%0,%1,%2,%3};"
                 : "+f"(c[0]), "+f"(c[1]), "+f"(c[2]), "+f"(c[3])
                 : "r"(a[0]), "r"(a[1]), "r"(a[2]), "r"(a[3]), "r"(b[0]), "r"(b[1]));
}

// ---------------------------------------------------------------------------
// Init: rope table + fp16 conversion of x / W_qkv / W_out, one kernel.
// ---------------------------------------------------------------------------
#define NX8  (BSZ*SEQ*DM/8)
#define NWQ8 (3*DM*DM/8)
#define NWO8 (DM*DM/8)
#define ROPE_BLOCKS (SEQ*32/256)                       // 256
#define INIT_BLOCKS (ROPE_BLOCKS + (NX8+NWQ8+NWO8)/256)

__global__ __launch_bounds__(256) void init_kernel(
    const float4* __restrict__ x, const float4* __restrict__ wq,
    const float4* __restrict__ wo)
{
    int bid = blockIdx.x;
    if (bid < ROPE_BLOCKS) {
        int i = bid * 256 + threadIdx.x;               // SEQ*32 entries
        int m = i >> 5, p = i & 31;
        float theta = powf(10000.0f, -(float)p / 32.0f);
        float s, c; sincosf((float)m * theta, &s, &c);
        g_rope[i] = make_float2(c, s);
        return;
    }
    int i = (bid - ROPE_BLOCKS) * 256 + threadIdx.x;
    const float4* src; __half* dst; int o;
    if (i < NX8)              { src = x;  dst = g_x;  o = i; }
    else if (i < NX8 + NWQ8)  { src = wq; dst = g_wq; o = i - NX8; }
    else                      { src = wo; dst = g_wo; o = i - NX8 - NWQ8; }
    float4 a = src[(size_t)o * 2], b = src[(size_t)o * 2 + 1];
    __half2 h[4];
    h[0] = __floats2half2_rn(a.x, a.y); h[1] = __floats2half2_rn(a.z, a.w);
    h[2] = __floats2half2_rn(b.x, b.y); h[3] = __floats2half2_rn(b.z, b.w);
    *(uint4*)(dst + (size_t)o * 8) = *(uint4*)h;
}

// ---------------------------------------------------------------------------
// GEMM core (fp16, best-known config): C = A @ B^T, CTA tile 128x128,
// k-chunk 64 (4 x k16 mma), 16 chunks fully unrolled, 3-stage cp.async,
// one barrier per chunk. 8 warps (2x4), warp tile 64x32.
// ---------------------------------------------------------------------------
#define GEMM_SMEM (6*128*72*2)

#define GEMM_PREFETCH(st, k0)                                                  \
    do {                                                                       \
        _Pragma("unroll")                                                      \
        for (int i_ = 0; i_ < 4; i_++) {                                       \
            int r_ = cr + i_ * 32;                                             \
            cp16(saddr(&As[st][r_][cq]), Abase + (size_t)r_ * DM + (k0) + cq); \
            cp16(saddr(&Bs[st][r_][cq]), Bbase + (size_t)r_ * DM + (k0) + cq); \
        }                                                                      \
        CP_COMMIT();                                                           \
    } while (0)

#define GEMM_PIPELINE(AbaseE, BbaseE)                                          \
    const int lane = threadIdx.x & 31;                                         \
    const int wid  = threadIdx.x >> 5;                                         \
    const int wm = wid >> 2, wn = wid & 3;                                     \
    extern __shared__ __half hsm[];                                            \
    __half (*As)[128][72] = (__half(*)[128][72])(hsm);                         \
    __half (*Bs)[128][72] = (__half(*)[128][72])(hsm + 3*128*72);              \
    float acc[4][4][4] = {};                                                   \
    const int cr = threadIdx.x >> 3;        /* 0..31 */                        \
    const int cq = (threadIdx.x & 7) * 8;   /* halves, 16B granule */          \
    const __half* Abase = (AbaseE);                                            \
    const __half* Bbase = (BbaseE);                                            \
    GEMM_PREFETCH(0, 0);                                                       \
    GEMM_PREFETCH(1, 64);                                                      \
    _Pragma("unroll")                                                          \
    for (int it = 0; it < 16; it++) {                                          \
        if (it + 2 < 16) { CP_WAIT(1); } else { CP_WAIT(0); }                  \
        __syncthreads();                                                       \
        if (it + 2 < 16) GEMM_PREFETCH((it + 2) % 3, (it + 2) * 64);           \
        const int cur = it % 3;                                                \
        _Pragma("unroll")                                                      \
        for (int kk = 0; kk < 4; kk++) {                                       \
            const int koff = kk*16 + ((lane >> 4) << 3);                       \
            unsigned a[4][4];                                                  \
            _Pragma("unroll")                                                  \
            for (int ma = 0; ma < 4; ma++)                                     \
                ldsm_x4(a[ma][0], a[ma][1], a[ma][2], a[ma][3],                \
                        saddr(&As[cur][wm*64 + ma*16 + (lane & 15)][koff]));   \
            unsigned b[4][2];                                                  \
            _Pragma("unroll")                                                  \
            for (int pr = 0; pr < 2; pr++) {                                   \
                unsigned r0, r1, r2, r3;                                       \
                ldsm_x4(r0, r1, r2, r3,                                        \
                        saddr(&Bs[cur][wn*32 + pr*16 + (lane & 15)][koff]));   \
                b[pr*2][0]   = r0; b[pr*2][1]   = r2;                          \
                b[pr*2+1][0] = r1; b[pr*2+1][1] = r3;                          \
            }                                                                  \
            _Pragma("unroll")                                                  \
            for (int ma = 0; ma < 4; ma++)                                     \
                _Pragma("unroll")                                              \
                for (int na = 0; na < 4; na++)                                 \
                    mma_f16(acc[ma][na], a[ma], b[na]);                        \
        }                                                                      \
    }

// ---------------------------------------------------------------------------
// QKV GEMM + bias + RoPE + scatter (fp16 outputs; V transposed).
// Q is additionally scaled by EXP_C so flash's exp is a bare ex2.
// ---------------------------------------------------------------------------
__global__ __launch_bounds__(256, 2) void qkv_kernel(const float* __restrict__ bias)
{
    const int m0 = blockIdx.y * 128;
    const int n0 = blockIdx.x * 128;

    GEMM_PIPELINE(g_x + (size_t)m0 * DM, g_wq + (size_t)n0 * DM)

    const int gid = lane >> 2, tig = lane & 3;
    const int which = n0 >> 10;                         // 0=q,1=k,2=v
    const int bq = m0 >> 11;
    const int s_base = (m0 & (SEQ-1)) + wm * 64;
    const int col_local = (n0 & 1023) + wn * 32;
    const int head = col_local >> 6;
    const int d0 = col_local & 63;
    const size_t bh = (size_t)(bq * NH + head);
    const float qscale = (which == 0) ? EXP_C : 1.0f;

    #pragma unroll
    for (int na = 0; na < 4; na++) {
        const int d = d0 + na*8 + 2*tig;
        const int ncol_g = n0 + wn*32 + na*8 + 2*tig;
        const float b0v = bias[ncol_g], b1v = bias[ncol_g + 1];
        const int p = d >> 1;
        #pragma unroll
        for (int ma = 0; ma < 4; ma++) {
            int s_lo = s_base + ma*16 + gid;
            const int r_lo = s_lo * 32;                 // rope row base (hoisted)
            float v0 = acc[ma][na][0] + b0v;
            float v1 = acc[ma][na][1] + b1v;
            float u0 = acc[ma][na][2] + b0v;
            float u1 = acc[ma][na][3] + b1v;
            if (which == 2) {
                __half* vt = g_vt + bh * (size_t)(HD * SEQ);
                vt[(size_t)d     * SEQ + s_lo    ] = __float2half_rn(v0);
                vt[(size_t)(d+1) * SEQ + s_lo    ] = __float2half_rn(v1);
                vt[(size_t)d     * SEQ + s_lo + 8] = __float2half_rn(u0);
                vt[(size_t)(d+1) * SEQ + s_lo + 8] = __float2half_rn(u1);
            } else {
                __half* dst = (which == 0 ? g_q : g_k) + bh * (size_t)(SEQ * HD);
                float2 rl = g_rope[r_lo + p];
                float2 rh = g_rope[r_lo + 256 + p];     // (s_lo+8)*32 = r_lo+256
                *(__half2*)&dst[(size_t)s_lo * HD + d] =
                    __floats2half2_rn((v0*rl.x - v1*rl.y) * qscale,
                                      (v1*rl.x + v0*rl.y) * qscale);
                *(__half2*)&dst[(size_t)(s_lo+8) * HD + d] =
                    __floats2half2_rn((u0*rh.x - u1*rh.y) * qscale,
                                      (u1*rh.x + u0*rh.y) * qscale);
            }
        }
    }
}

// ---------------------------------------------------------------------------
// Out-proj GEMM: out(fp32) = g_ao @ W_out^T + b_out
// ---------------------------------------------------------------------------
__global__ __launch_bounds__(256, 2) void out_kernel(
    const float* __restrict__ bias, float* __restrict__ out)
{
    const int m0 = blockIdx.y * 128;
    const int n0 = blockIdx.x * 128;

    GEMM_PIPELINE(g_ao + (size_t)m0 * DM, g_wo + (size_t)n0 * DM)

    const int gid = lane >> 2, tig = lane & 3;
    #pragma unroll
    for (int na = 0; na < 4; na++) {
        int col = n0 + wn*32 + na*8 + 2*tig;
        float b0v = bias[col], b1v = bias[col + 1];
        #pragma unroll
        for (int ma = 0; ma < 4; ma++) {
            int row = m0 + wm*64 + ma*16 + gid;
            out[(size_t)row       * DM + col    ] = acc[ma][na][0] + b0v;
            out[(size_t)row       * DM + col + 1] = acc[ma][na][1] + b1v;
            out[(size_t)(row + 8) * DM + col    ] = acc[ma][na][2] + b0v;
            out[(size_t)(row + 8) * DM + col + 1] = acc[ma][na][3] + b1v;
        }
    }
}

// ---------------------------------------------------------------------------
// Flash attention v7 (Round-11 best, measured 223.8us): 8 warps x 32 q-rows,
// Q + P fragments in registers, 64-key DOUBLE-buffered K/V tiles, one barrier
// per 64 keys; q pre-scaled by EXP_C so exp is a bare fp32 ex2.
// smem halves: Qs[256][72] | Ks[2][64][72] | Vs[2][64][72]  = 73728 bytes
// ---------------------------------------------------------------------------
#define FLH_K  (256*72)
#define FLH_V  (FLH_K + 2*64*72)
#define FL_SMEM ((FLH_V + 2*64*72) * 2)   // 73728 bytes

// One 32-key half: keys H..H+31 of the CUR buffer.
#define FLASH_HALF(CUR, H)                                                    \
    {                                                                         \
        float S[2][4][4] = {};                                                \
        /* ---- S_A: keys H+0..H+15 ---- */                                   \
        _Pragma("unroll")                                                     \
        for (int kk = 0; kk < 4; kk++) {                                      \
            const int koff = kk*16 + ((lane >> 4) << 3);                      \
            unsigned r0, r1, r2, r3;                                          \
            ldsm_x4(r0, r1, r2, r3,                                           \
                    saddr(&Ks[CUR][(H) + (lane & 15)][koff]));                \
            unsigned b0[2] = {r0, r2}, b1[2] = {r1, r3};                      \
            _Pragma("unroll")                                                 \
            for (int t = 0; t < 2; t++) {                                     \
                mma_f16(S[t][0], aq[t][kk], b0);                              \
                mma_f16(S[t][1], aq[t][kk], b1);                              \
            }                                                                 \
        }                                                                     \
        /* ---- S_B: keys H+16..H+31 ---- */                                  \
        _Pragma("unroll")                                                     \
        for (int kk = 0; kk < 4; kk++) {                                      \
            const int koff = kk*16 + ((lane >> 4) << 3);                      \
            unsigned r0, r1, r2, r3;                                          \
            ldsm_x4(r0, r1, r2, r3,                                           \
                    saddr(&Ks[CUR][(H) + 16 + (lane & 15)][koff]));           \
            unsigned b0[2] = {r0, r2}, b1[2] = {r1, r3};                      \
            _Pragma("unroll")                                                 \
            for (int t = 0; t < 2; t++) {                                     \
                mma_f16(S[t][2], aq[t][kk], b0);                              \
                mma_f16(S[t][3], aq[t][kk], b1);                              \
            }                                                                 \
        }                                                                     \
        /* ---- exp_A: P (first 16 keys) -> PV A-fragments ---- */            \
        unsigned pa[2][4];                                                    \
        _Pragma("unroll")                                                     \
        for (int t = 0; t < 2; t++) {                                         \
            float p00 = fast_ex2(S[t][0][0]);                                 \
            float p01 = fast_ex2(S[t][0][1]);                                 \
            float p02 = fast_ex2(S[t][0][2]);                                 \
            float p03 = fast_ex2(S[t][0][3]);                                 \
            float p10 = fast_ex2(S[t][1][0]);                                 \
            float p11 = fast_ex2(S[t][1][1]);                                 \
            float p12 = fast_ex2(S[t][1][2]);                                 \
            float p13 = fast_ex2(S[t][1][3]);                                 \
            rs[t][0] += (p00 + p01) + (p10 + p11);                            \
            rs[t][1] += (p02 + p03) + (p12 + p13);                            \
            pa[t][0] = packh2(p00, p01);                                      \
            pa[t][1] = packh2(p02, p03);                                      \
            pa[t][2] = packh2(p10, p11);                                      \
            pa[t][3] = packh2(p12, p13);                                      \
        }                                                                     \
        /* ---- PV_A: V s-cols H..H+15 ---- */                                \
        {                                                                     \
            const int koff = (H) + ((lane >> 4) << 3);                        \
            _Pragma("unroll")                                                 \
            for (int pr = 0; pr < 4; pr++) {                                  \
                unsigned r0, r1, r2, r3;                                      \
                ldsm_x4(r0, r1, r2, r3,                                       \
                        saddr(&Vs[CUR][pr*16 + (lane & 15)][koff]));          \
                unsigned b0[2] = {r0, r2}, b1[2] = {r1, r3};                  \
                _Pragma("unroll")                                             \
                for (int t = 0; t < 2; t++) {                                 \
                    mma_f16(O[t][pr*2],   pa[t], b0);                         \
                    mma_f16(O[t][pr*2+1], pa[t], b1);                         \
                }                                                             \
            }                                                                 \
        }                                                                     \
        /* ---- exp_B: P (second 16 keys), overlaps PV_A ---- */              \
        unsigned pb[2][4];                                                    \
        _Pragma("unroll")                                                     \
        for (int t = 0; t < 2; t++) {                                         \
            float p00 = fast_ex2(S[t][2][0]);                                 \
            float p01 = fast_ex2(S[t][2][1]);                                 \
            float p02 = fast_ex2(S[t][2][2]);                                 \
            float p03 = fast_ex2(S[t][2][3]);                                 \
            float p10 = fast_ex2(S[t][3][0]);                                 \
            float p11 = fast_ex2(S[t][3][1]);                                 \
            float p12 = fast_ex2(S[t][3][2]);                                 \
            float p13 = fast_ex2(S[t][3][3]);                                 \
            rs[t][0] += (p00 + p01) + (p10 + p11);                            \
            rs[t][1] += (p02 + p03) + (p12 + p13);                            \
            pb[t][0] = packh2(p00, p01);                                      \
            pb[t][1] = packh2(p02, p03);                                      \
            pb[t][2] = packh2(p10, p11);                                      \
            pb[t][3] = packh2(p12, p13);                                      \
        }                                                                     \
        /* ---- PV_B: V s-cols H+16..H+31 ---- */                             \
        {                                                                     \
            const int koff = (H) + 16 + ((lane >> 4) << 3);                   \
            _Pragma("unroll")                                                 \
            for (int pr = 0; pr < 4; pr++) {                                  \
                unsigned r0, r1, r2, r3;                                      \
                ldsm_x4(r0, r1, r2, r3,                                       \
                        saddr(&Vs[CUR][pr*16 + (lane & 15)][koff]));          \
                unsigned b0[2] = {r0, r2}, b1[2] = {r1, r3};                  \
                _Pragma("unroll")                                             \
                for (int t = 0; t < 2; t++) {                                 \
                    mma_f16(O[t][pr*2],   pb[t], b0);                         \
                    mma_f16(O[t][pr*2+1], pb[t], b1);                         \
                }                                                             \
            }                                                                 \
        }                                                                     \
    }

// One 64-key tile: wait, prefetch next buffer, compute two halves.
#define FLASH_TILE(CUR, IT)                                                   \
    {                                                                         \
        CP_WAIT(0);                                                           \
        __syncthreads();                                                      \
        if ((IT) + 1 < SEQ / 64) {                                            \
            const int kt_ = ((IT) + 1) * 64;                                  \
            _Pragma("unroll")                                                 \
            for (int i_ = 0; i_ < 2; i_++) {                                  \
                cp16(kdst[(CUR) ^ 1] + i_ * (32*72*2),                        \
                     kb + (size_t)(kt_ + kr0 + i_ * 32) * HD + kq0);          \
                cp16(vdst[(CUR) ^ 1] + i_ * (32*72*2),                        \
                     vtb + (size_t)(vr0 + i_ * 32) * SEQ + kt_ + vq0);        \
            }                                                                 \
            CP_COMMIT();                                                      \
        }                                                                     \
        FLASH_HALF(CUR, 0)                                                    \
        FLASH_HALF(CUR, 32)                                                   \
    }

__global__ __launch_bounds__(256, 2) void flash_kernel()
{
    extern __shared__ __half fsm[];
    __half (*Qs)[72]     = (__half(*)[72])(fsm);
    __half (*Ks)[64][72] = (__half(*)[64][72])(fsm + FLH_K);
    __half (*Vs)[64][72] = (__half(*)[64][72])(fsm + FLH_V);

    const int tid = threadIdx.x;
    const int lane = tid & 31;
    const int wid = tid >> 5;                 // 0..7
    const int gid = lane >> 2, tig = lane & 3;
    const int q0 = blockIdx.x * 256;
    const int bh = blockIdx.y;

    const __half* qb  = g_q  + (size_t)bh * SEQ * HD + (size_t)q0 * HD;
    const __half* kb  = g_k  + (size_t)bh * SEQ * HD;
    const __half* vtb = g_vt + (size_t)bh * HD * SEQ;

    // prefetch geometry (loop-invariant): each thread covers rows r0 and r0+32
    const int kr0 = tid >> 3, kq0 = (tid & 7) * 8;   // K: [key][d], 64x64 halves
    const int vr0 = tid >> 3, vq0 = (tid & 7) * 8;   // V: [d][s],   64x64 halves
    const unsigned kdst[2] = { saddr(&Ks[0][kr0][kq0]), saddr(&Ks[1][kr0][kq0]) };
    const unsigned vdst[2] = { saddr(&Vs[0][vr0][vq0]), saddr(&Vs[1][vr0][vq0]) };

    // K/V tile 0 + Q tile -> smem (one cp.async group; 256 threads)
    {
        #pragma unroll
        for (int i = 0; i < 2; i++) {
            cp16(kdst[0] + i * (32*72*2), kb + (size_t)(kr0 + i * 32) * HD + kq0);
            cp16(vdst[0] + i * (32*72*2), vtb + (size_t)(vr0 + i * 32) * SEQ + vq0);
        }
        #pragma unroll
        for (int i = 0; i < 8; i++) {
            int c = tid + i * 256;
            int qr = c >> 3, qq = (c & 7) * 8;          // 256 x 64 halves
            cp16(saddr(&Qs[qr][qq]), qb + (size_t)qr * HD + qq);
        }
        CP_COMMIT();
    }
    CP_WAIT(0);
    __syncthreads();

    // Q fragments -> registers: 2 m-tiles x 4 k16-chunks per warp
    unsigned aq[2][4][4];
    #pragma unroll
    for (int t = 0; t < 2; t++)
        #pragma unroll
        for (int kk = 0; kk < 4; kk++)
            ldsm_x4(aq[t][kk][0], aq[t][kk][1], aq[t][kk][2], aq[t][kk][3],
                    saddr(&Qs[wid*32 + t*16 + (lane & 15)]
                             [kk*16 + ((lane >> 4) << 3)]));

    float O[2][8][4] = {};
    float rs[2][2] = {};

    for (int it = 0; it < SEQ / 64; it += 2) {
        FLASH_TILE(0, it)
        FLASH_TILE(1, it + 1)
    }

    // final row-sum reduction, writeback (fp16 feeds the out GEMM)
    const int b = bh >> 4, h = bh & 15;
    #pragma unroll
    for (int t = 0; t < 2; t++) {
        float r0 = rs[t][0], r1 = rs[t][1];
        r0 += __shfl_xor_sync(0xffffffffu, r0, 1);
        r0 += __shfl_xor_sync(0xffffffffu, r0, 2);
        r1 += __shfl_xor_sync(0xffffffffu, r1, 1);
        r1 += __shfl_xor_sync(0xffffffffu, r1, 2);
        const float inv0 = 1.0f / r0, inv1 = 1.0f / r1;
        const int s_lo = q0 + wid*32 + t*16 + gid;
        #pragma unroll
        for (int n = 0; n < 8; n++) {
            int d = h*64 + n*8 + 2*tig;
            *(__half2*)&g_ao[(size_t)(b*SEQ + s_lo    ) * DM + d] =
                __floats2half2_rn(O[t][n][0] * inv0, O[t][n][1] * inv0);
            *(__half2*)&g_ao[(size_t)(b*SEQ + s_lo + 8) * DM + d] =
                __floats2half2_rn(O[t][n][2] * inv1, O[t][n][3] * inv1);
        }
    }
}

// ---------------------------------------------------------------------------
extern "C" void kernel_launch(void* const* d_in, const int* in_sizes, int n_in,
                              void* d_out, int out_size)
{
    const float* x    = (const float*)d_in[0];
    const float* Wqkv = (const float*)d_in[1];
    const float* bqkv = (const float*)d_in[2];
    const float* Wout = (const float*)d_in[3];
    const float* bout = (const float*)d_in[4];
    float* out = (float*)d_out;

    cudaFuncSetAttribute(qkv_kernel,
                         cudaFuncAttributeMaxDynamicSharedMemorySize, GEMM_SMEM);
    cudaFuncSetAttribute(out_kernel,
                         cudaFuncAttributeMaxDynamicSharedMemorySize, GEMM_SMEM);
    cudaFuncSetAttribute(flash_kernel,
                         cudaFuncAttributeMaxDynamicSharedMemorySize, FL_SMEM);

    init_kernel<<<INIT_BLOCKS, 256>>>(
        (const float4*)x, (const float4*)Wqkv, (const float4*)Wout);
    qkv_kernel<<<dim3(24, 64), 256, GEMM_SMEM>>>(bqkv);
    flash_kernel<<<dim3(SEQ / 256, 64), 256, FL_SMEM>>>();
    out_kernel<<<dim3(8, 64), 256, GEMM_SMEM>>>(bout, out);
}

// round 16
// speedup vs baseline: 1.5531x; 1.0121x over previous
#include <cuda_runtime.h>
#include <cuda_fp16.h>
#include <math.h>

#define BSZ 4
#define SEQ 2048
#define NH  16
#define HD  64
#define DM  1024
#define EXP_C 0.1803368801f   // 0.125 * log2(e), folded into q at the producer

// Scratch (device globals; no allocations allowed). All tensor operands fp16.
__device__ __half  g_x [BSZ*SEQ*DM];
__device__ __half  g_wq[3*DM*DM];
__device__ __half  g_wo[DM*DM];
__device__ __half  g_q [BSZ*NH*SEQ*HD];   // pre-scaled by EXP_C
__device__ __half  g_k [BSZ*NH*SEQ*HD];
__device__ __half  g_vt[BSZ*NH*HD*SEQ];   // V transposed: [bh][d][s]
__device__ __half  g_ao[BSZ*SEQ*DM];
__device__ float2  g_rope[SEQ*32];        // (cos,sin) per (pos, pair)

// ---------------------------------------------------------------------------
__device__ __forceinline__ float fast_ex2(float x) {
    float r; asm("ex2.approx.ftz.f32 %0, %1;" : "=f"(r) : "f"(x)); return r;
}
__device__ __forceinline__ unsigned packh2(float lo, float hi) {
    __half2 h = __floats2half2_rn(lo, hi);
    return *(unsigned*)&h;
}
__device__ __forceinline__ unsigned saddr(const void* p) {
    return (unsigned)__cvta_generic_to_shared(p);
}
__device__ __forceinline__ void cp16(unsigned d, const void* s) {
    asm volatile("cp.async.cg.shared.global [%0], [%1], 16;" :: "r"(d), "l"(s));
}
#define CP_COMMIT() asm volatile("cp.async.commit_group;")
#define CP_WAIT(n)  asm volatile("cp.async.wait_group %0;" :: "n"(n))

__device__ __forceinline__ void ldsm_x4(unsigned& r0, unsigned& r1,
                                        unsigned& r2, unsigned& r3, unsigned a) {
    asm volatile("ldmatrix.sync.aligned.m8n8.x4.shared.b16 {%0,%1,%2,%3}, [%4];"
                 : "=r"(r0), "=r"(r1), "=r"(r2), "=r"(r3) : "r"(a));
}
// fp16 mma, fp32 accumulate: D[16x8] += A[16x16] B[16x8]
__device__ __forceinline__ void mma_f16(float* c, const unsigned* a, const unsigned* b) {
    asm volatile("mma.sync.aligned.m16n8k16.row.col.f32.f16.f16.f32 "
                 "{%0,%1,%2,%3},{%4,%5,%6,%7},{%8,%9},{%0,%1,%2,%3};"
                 : "+f"(c[0]), "+f"(c[1]), "+f"(c[2]), "+f"(c[3])
                 : "r"(a[0]), "r"(a[1]), "r"(a[2]), "r"(a[3]), "r"(b[0]), "r"(b[1]));
}

// ---------------------------------------------------------------------------
// Init: rope table + fp16 conversion of x / W_qkv / W_out, one kernel.
// ---------------------------------------------------------------------------
#define NX8  (BSZ*SEQ*DM/8)
#define NWQ8 (3*DM*DM/8)
#define NWO8 (DM*DM/8)
#define ROPE_BLOCKS (SEQ*32/256)                       // 256
#define INIT_BLOCKS (ROPE_BLOCKS + (NX8+NWQ8+NWO8)/256)

__global__ __launch_bounds__(256) void init_kernel(
    const float4* __restrict__ x, const float4* __restrict__ wq,
    const float4* __restrict__ wo)
{
    int bid = blockIdx.x;
    if (bid < ROPE_BLOCKS) {
        int i = bid * 256 + threadIdx.x;               // SEQ*32 entries
        int m = i >> 5, p = i & 31;
        float theta = powf(10000.0f, -(float)p / 32.0f);
        float s, c; sincosf((float)m * theta, &s, &c);
        g_rope[i] = make_float2(c, s);
        return;
    }
    int i = (bid - ROPE_BLOCKS) * 256 + threadIdx.x;
    const float4* src; __half* dst; int o;
    if (i < NX8)              { src = x;  dst = g_x;  o = i; }
    else if (i < NX8 + NWQ8)  { src = wq; dst = g_wq; o = i - NX8; }
    else                      { src = wo; dst = g_wo; o = i - NX8 - NWQ8; }
    float4 a = src[(size_t)o * 2], b = src[(size_t)o * 2 + 1];
    __half2 h[4];
    h[0] = __floats2half2_rn(a.x, a.y); h[1] = __floats2half2_rn(a.z, a.w);
    h[2] = __floats2half2_rn(b.x, b.y); h[3] = __floats2half2_rn(b.z, b.w);
    *(uint4*)(dst + (size_t)o * 8) = *(uint4*)h;
}

// ---------------------------------------------------------------------------
// GEMM core (fp16, best-known config): C = A @ B^T, CTA tile 128x128,
// k-chunk 64 (4 x k16 mma), 16 chunks fully unrolled, 3-stage cp.async,
// one barrier per chunk. 8 warps (2x4), warp tile 64x32.
// ---------------------------------------------------------------------------
#define GEMM_SMEM (6*128*72*2)

#define GEMM_PREFETCH(st, k0)                                                  \
    do {                                                                       \
        _Pragma("unroll")                                                      \
        for (int i_ = 0; i_ < 4; i_++) {                                       \
            int r_ = cr + i_ * 32;                                             \
            cp16(saddr(&As[st][r_][cq]), Abase + (size_t)r_ * DM + (k0) + cq); \
            cp16(saddr(&Bs[st][r_][cq]), Bbase + (size_t)r_ * DM + (k0) + cq); \
        }                                                                      \
        CP_COMMIT();                                                           \
    } while (0)

#define GEMM_PIPELINE(AbaseE, BbaseE)                                          \
    const int lane = threadIdx.x & 31;                                         \
    const int wid  = threadIdx.x >> 5;                                         \
    const int wm = wid >> 2, wn = wid & 3;                                     \
    extern __shared__ __half hsm[];                                            \
    __half (*As)[128][72] = (__half(*)[128][72])(hsm);                         \
    __half (*Bs)[128][72] = (__half(*)[128][72])(hsm + 3*128*72);              \
    float acc[4][4][4] = {};                                                   \
    const int cr = threadIdx.x >> 3;        /* 0..31 */                        \
    const int cq = (threadIdx.x & 7) * 8;   /* halves, 16B granule */          \
    const __half* Abase = (AbaseE);                                            \
    const __half* Bbase = (BbaseE);                                            \
    GEMM_PREFETCH(0, 0);                                                       \
    GEMM_PREFETCH(1, 64);                                                      \
    _Pragma("unroll")                                                          \
    for (int it = 0; it < 16; it++) {                                          \
        if (it + 2 < 16) { CP_WAIT(1); } else { CP_WAIT(0); }                  \
        __syncthreads();                                                       \
        if (it + 2 < 16) GEMM_PREFETCH((it + 2) % 3, (it + 2) * 64);           \
        const int cur = it % 3;                                                \
        _Pragma("unroll")                                                      \
        for (int kk = 0; kk < 4; kk++) {                                       \
            const int koff = kk*16 + ((lane >> 4) << 3);                       \
            unsigned a[4][4];                                                  \
            _Pragma("unroll")                                                  \
            for (int ma = 0; ma < 4; ma++)                                     \
                ldsm_x4(a[ma][0], a[ma][1], a[ma][2], a[ma][3],                \
                        saddr(&As[cur][wm*64 + ma*16 + (lane & 15)][koff]));   \
            unsigned b[4][2];                                                  \
            _Pragma("unroll")                                                  \
            for (int pr = 0; pr < 2; pr++) {                                   \
                unsigned r0, r1, r2, r3;                                       \
                ldsm_x4(r0, r1, r2, r3,                                        \
                        saddr(&Bs[cur][wn*32 + pr*16 + (lane & 15)][koff]));   \
                b[pr*2][0]   = r0; b[pr*2][1]   = r2;                          \
                b[pr*2+1][0] = r1; b[pr*2+1][1] = r3;                          \
            }                                                                  \
            _Pragma("unroll")                                                  \
            for (int ma = 0; ma < 4; ma++)                                     \
                _Pragma("unroll")                                              \
                for (int na = 0; na < 4; na++)                                 \
                    mma_f16(acc[ma][na], a[ma], b[na]);                        \
        }                                                                      \
    }

// ---------------------------------------------------------------------------
// QKV GEMM + bias + RoPE + scatter (fp16 outputs; V transposed).
// Q is additionally scaled by EXP_C so flash's exp is a bare ex2.
// ---------------------------------------------------------------------------
__global__ __launch_bounds__(256, 2) void qkv_kernel(const float* __restrict__ bias)
{
    const int m0 = blockIdx.y * 128;
    const int n0 = blockIdx.x * 128;

    GEMM_PIPELINE(g_x + (size_t)m0 * DM, g_wq + (size_t)n0 * DM)

    const int gid = lane >> 2, tig = lane & 3;
    const int which = n0 >> 10;                         // 0=q,1=k,2=v
    const int bq = m0 >> 11;
    const int s_base = (m0 & (SEQ-1)) + wm * 64;
    const int col_local = (n0 & 1023) + wn * 32;
    const int head = col_local >> 6;
    const int d0 = col_local & 63;
    const size_t bh = (size_t)(bq * NH + head);
    const float qscale = (which == 0) ? EXP_C : 1.0f;

    #pragma unroll
    for (int na = 0; na < 4; na++) {
        const int d = d0 + na*8 + 2*tig;
        const int ncol_g = n0 + wn*32 + na*8 + 2*tig;
        const float b0v = __ldg(&bias[ncol_g]), b1v = __ldg(&bias[ncol_g + 1]);
        const int p = d >> 1;
        #pragma unroll
        for (int ma = 0; ma < 4; ma++) {
            int s_lo = s_base + ma*16 + gid;
            const int r_lo = s_lo * 32;                 // rope row base (hoisted)
            float v0 = acc[ma][na][0] + b0v;
            float v1 = acc[ma][na][1] + b1v;
            float u0 = acc[ma][na][2] + b0v;
            float u1 = acc[ma][na][3] + b1v;
            if (which == 2) {
                __half* vt = g_vt + bh * (size_t)(HD * SEQ);
                vt[(size_t)d     * SEQ + s_lo    ] = __float2half_rn(v0);
                vt[(size_t)(d+1) * SEQ + s_lo    ] = __float2half_rn(v1);
                vt[(size_t)d     * SEQ + s_lo + 8] = __float2half_rn(u0);
                vt[(size_t)(d+1) * SEQ + s_lo + 8] = __float2half_rn(u1);
            } else {
                __half* dst = (which == 0 ? g_q : g_k) + bh * (size_t)(SEQ * HD);
                float2 rl = g_rope[r_lo + p];
                float2 rh = g_rope[r_lo + 256 + p];     // (s_lo+8)*32 = r_lo+256
                *(__half2*)&dst[(size_t)s_lo * HD + d] =
                    __floats2half2_rn((v0*rl.x - v1*rl.y) * qscale,
                                      (v1*rl.x + v0*rl.y) * qscale);
                *(__half2*)&dst[(size_t)(s_lo+8) * HD + d] =
                    __floats2half2_rn((u0*rh.x - u1*rh.y) * qscale,
                                      (u1*rh.x + u0*rh.y) * qscale);
            }
        }
    }
}

// ---------------------------------------------------------------------------
// Out-proj GEMM: out(fp32) = g_ao @ W_out^T + b_out (vectorized epilogue)
// ---------------------------------------------------------------------------
__global__ __launch_bounds__(256, 2) void out_kernel(
    const float* __restrict__ bias, float* __restrict__ out)
{
    const int m0 = blockIdx.y * 128;
    const int n0 = blockIdx.x * 128;

    GEMM_PIPELINE(g_ao + (size_t)m0 * DM, g_wo + (size_t)n0 * DM)

    const int gid = lane >> 2, tig = lane & 3;
    #pragma unroll
    for (int na = 0; na < 4; na++) {
        int col = n0 + wn*32 + na*8 + 2*tig;
        const float2 bv = *(const float2*)&bias[col];
        #pragma unroll
        for (int ma = 0; ma < 4; ma++) {
            int row = m0 + wm*64 + ma*16 + gid;
            *(float2*)&out[(size_t)row * DM + col] =
                make_float2(acc[ma][na][0] + bv.x, acc[ma][na][1] + bv.y);
            *(float2*)&out[(size_t)(row + 8) * DM + col] =
                make_float2(acc[ma][na][2] + bv.x, acc[ma][na][3] + bv.y);
        }
    }
}

// ---------------------------------------------------------------------------
// Flash attention v7 (measured best, 223.8us): 8 warps x 32 q-rows,
// Q + P fragments in registers, 64-key DOUBLE-buffered K/V tiles, one barrier
// per 64 keys; q pre-scaled by EXP_C so exp is a bare fp32 ex2.
// smem halves: Qs[256][72] | Ks[2][64][72] | Vs[2][64][72]  = 73728 bytes
// ---------------------------------------------------------------------------
#define FLH_K  (256*72)
#define FLH_V  (FLH_K + 2*64*72)
#define FL_SMEM ((FLH_V + 2*64*72) * 2)   // 73728 bytes

// One 32-key half: keys H..H+31 of the CUR buffer.
#define FLASH_HALF(CUR, H)                                                    \
    {                                                                         \
        float S[2][4][4] = {};                                                \
        /* ---- S_A: keys H+0..H+15 ---- */                                   \
        _Pragma("unroll")                                                     \
        for (int kk = 0; kk < 4; kk++) {                                      \
            const int koff = kk*16 + ((lane >> 4) << 3);                      \
            unsigned r0, r1, r2, r3;                                          \
            ldsm_x4(r0, r1, r2, r3,                                           \
                    saddr(&Ks[CUR][(H) + (lane & 15)][koff]));                \
            unsigned b0[2] = {r0, r2}, b1[2] = {r1, r3};                      \
            _Pragma("unroll")                                                 \
            for (int t = 0; t < 2; t++) {                                     \
                mma_f16(S[t][0], aq[t][kk], b0);                              \
                mma_f16(S[t][1], aq[t][kk], b1);                              \
            }                                                                 \
        }                                                                     \
        /* ---- S_B: keys H+16..H+31 ---- */                                  \
        _Pragma("unroll")                                                     \
        for (int kk = 0; kk < 4; kk++) {                                      \
            const int koff = kk*16 + ((lane >> 4) << 3);                      \
            unsigned r0, r1, r2, r3;                                          \
            ldsm_x4(r0, r1, r2, r3,                                           \
                    saddr(&Ks[CUR][(H) + 16 + (lane & 15)][koff]));           \
            unsigned b0[2] = {r0, r2}, b1[2] = {r1, r3};                      \
            _Pragma("unroll")                                                 \
            for (int t = 0; t < 2; t++) {                                     \
                mma_f16(S[t][2], aq[t][kk], b0);                              \
                mma_f16(S[t][3], aq[t][kk], b1);                              \
            }                                                                 \
        }                                                                     \
        /* ---- exp_A: P (first 16 keys) -> PV A-fragments ---- */            \
        unsigned pa[2][4];                                                    \
        _Pragma("unroll")                                                     \
        for (int t = 0; t < 2; t++) {                                         \
            float p00 = fast_ex2(S[t][0][0]);                                 \
            float p01 = fast_ex2(S[t][0][1]);                                 \
            float p02 = fast_ex2(S[t][0][2]);                                 \
            float p03 = fast_ex2(S[t][0][3]);                                 \
            float p10 = fast_ex2(S[t][1][0]);                                 \
            float p11 = fast_ex2(S[t][1][1]);                                 \
            float p12 = fast_ex2(S[t][1][2]);                                 \
            float p13 = fast_ex2(S[t][1][3]);                                 \
            rs[t][0] += (p00 + p01) + (p10 + p11);                            \
            rs[t][1] += (p02 + p03) + (p12 + p13);                            \
            pa[t][0] = packh2(p00, p01);                                      \
            pa[t][1] = packh2(p02, p03);                                      \
            pa[t][2] = packh2(p10, p11);                                      \
            pa[t][3] = packh2(p12, p13);                                      \
        }                                                                     \
        /* ---- PV_A: V s-cols H..H+15 ---- */                                \
        {                                                                     \
            const int koff = (H) + ((lane >> 4) << 3);                        \
            _Pragma("unroll")                                                 \
            for (int pr = 0; pr < 4; pr++) {                                  \
                unsigned r0, r1, r2, r3;                                      \
                ldsm_x4(r0, r1, r2, r3,                                       \
                        saddr(&Vs[CUR][pr*16 + (lane & 15)][koff]));          \
                unsigned b0[2] = {r0, r2}, b1[2] = {r1, r3};                  \
                _Pragma("unroll")                                             \
                for (int t = 0; t < 2; t++) {                                 \
                    mma_f16(O[t][pr*2],   pa[t], b0);                         \
                    mma_f16(O[t][pr*2+1], pa[t], b1);                         \
                }                                                             \
            }                                                                 \
        }                                                                     \
        /* ---- exp_B: P (second 16 keys), overlaps PV_A ---- */              \
        unsigned pb[2][4];                                                    \
        _Pragma("unroll")                                                     \
        for (int t = 0; t < 2; t++) {                                         \
            float p00 = fast_ex2(S[t][2][0]);                                 \
            float p01 = fast_ex2(S[t][2][1]);                                 \
            float p02 = fast_ex2(S[t][2][2]);                                 \
            float p03 = fast_ex2(S[t][2][3]);                                 \
            float p10 = fast_ex2(S[t][3][0]);                                 \
            float p11 = fast_ex2(S[t][3][1]);                                 \
            float p12 = fast_ex2(S[t][3][2]);                                 \
            float p13 = fast_ex2(S[t][3][3]);                                 \
            rs[t][0] += (p00 + p01) + (p10 + p11);                            \
            rs[t][1] += (p02 + p03) + (p12 + p13);                            \
            pb[t][0] = packh2(p00, p01);                                      \
            pb[t][1] = packh2(p02, p03);                                      \
            pb[t][2] = packh2(p10, p11);                                      \
            pb[t][3] = packh2(p12, p13);                                      \
        }                                                                     \
        /* ---- PV_B: V s-cols H+16..H+31 ---- */                             \
        {                                                                     \
            const int koff = (H) + 16 + ((lane >> 4) << 3);                   \
            _Pragma("unroll")                                                 \
            for (int pr = 0; pr < 4; pr++) {                                  \
                unsigned r0, r1, r2, r3;                                      \
                ldsm_x4(r0, r1, r2, r3,                                       \
                        saddr(&Vs[CUR][pr*16 + (lane & 15)][koff]));          \
                unsigned b0[2] = {r0, r2}, b1[2] = {r1, r3};                  \
                _Pragma("unroll")                                             \
                for (int t = 0; t < 2; t++) {                                 \
                    mma_f16(O[t][pr*2],   pb[t], b0);                         \
                    mma_f16(O[t][pr*2+1], pb[t], b1);                         \
                }                                                             \
            }                                                                 \
        }                                                                     \
    }

// One 64-key tile: wait, prefetch next buffer, compute two halves.
#define FLASH_TILE(CUR, IT)                                                   \
    {                                                                         \
        CP_WAIT(0);                                                           \
        __syncthreads();                                                      \
        if ((IT) + 1 < SEQ / 64) {                                            \
            const int kt_ = ((IT) + 1) * 64;                                  \
            _Pragma("unroll")                                                 \
            for (int i_ = 0; i_ < 2; i_++) {                                  \
                cp16(kdst[(CUR) ^ 1] + i_ * (32*72*2),                        \
                     kb + (size_t)(kt_ + kr0 + i_ * 32) * HD + kq0);          \
                cp16(vdst[(CUR) ^ 1] + i_ * (32*72*2),                        \
                     vtb + (size_t)(vr0 + i_ * 32) * SEQ + kt_ + vq0);        \
            }                                                                 \
            CP_COMMIT();                                                      \
        }                                                                     \
        FLASH_HALF(CUR, 0)                                                    \
        FLASH_HALF(CUR, 32)                                                   \
    }

__global__ __launch_bounds__(256, 2) void flash_kernel()
{
    extern __shared__ __half fsm[];
    __half (*Qs)[72]     = (__half(*)[72])(fsm);
    __half (*Ks)[64][72] = (__half(*)[64][72])(fsm + FLH_K);
    __half (*Vs)[64][72] = (__half(*)[64][72])(fsm + FLH_V);

    const int tid = threadIdx.x;
    const int lane = tid & 31;
    const int wid = tid >> 5;                 // 0..7
    const int gid = lane >> 2, tig = lane & 3;
    const int q0 = blockIdx.x * 256;
    const int bh = blockIdx.y;

    const __half* qb  = g_q  + (size_t)bh * SEQ * HD + (size_t)q0 * HD;
    const __half* kb  = g_k  + (size_t)bh * SEQ * HD;
    const __half* vtb = g_vt + (size_t)bh * HD * SEQ;

    // prefetch geometry (loop-invariant): each thread covers rows r0 and r0+32
    const int kr0 = tid >> 3, kq0 = (tid & 7) * 8;   // K: [key][d], 64x64 halves
    const int vr0 = tid >> 3, vq0 = (tid & 7) * 8;   // V: [d][s],   64x64 halves
    const unsigned kdst[2] = { saddr(&Ks[0][kr0][kq0]), saddr(&Ks[1][kr0][kq0]) };
    const unsigned vdst[2] = { saddr(&Vs[0][vr0][vq0]), saddr(&Vs[1][vr0][vq0]) };

    // K/V tile 0 + Q tile -> smem (one cp.async group; 256 threads)
    {
        #pragma unroll
        for (int i = 0; i < 2; i++) {
            cp16(kdst[0] + i * (32*72*2), kb + (size_t)(kr0 + i * 32) * HD + kq0);
            cp16(vdst[0] + i * (32*72*2), vtb + (size_t)(vr0 + i * 32) * SEQ + vq0);
        }
        #pragma unroll
        for (int i = 0; i < 8; i++) {
            int c = tid + i * 256;
            int qr = c >> 3, qq = (c & 7) * 8;          // 256 x 64 halves
            cp16(saddr(&Qs[qr][qq]), qb + (size_t)qr * HD + qq);
        }
        CP_COMMIT();
    }
    CP_WAIT(0);
    __syncthreads();

    // Q fragments -> registers: 2 m-tiles x 4 k16-chunks per warp
    unsigned aq[2][4][4];
    #pragma unroll
    for (int t = 0; t < 2; t++)
        #pragma unroll
        for (int kk = 0; kk < 4; kk++)
            ldsm_x4(aq[t][kk][0], aq[t][kk][1], aq[t][kk][2], aq[t][kk][3],
                    saddr(&Qs[wid*32 + t*16 + (lane & 15)]
                             [kk*16 + ((lane >> 4) << 3)]));

    float O[2][8][4] = {};
    float rs[2][2] = {};

    for (int it = 0; it < SEQ / 64; it += 2) {
        FLASH_TILE(0, it)
        FLASH_TILE(1, it + 1)
    }

    // final row-sum reduction, writeback (fp16 feeds the out GEMM)
    const int b = bh >> 4, h = bh & 15;
    #pragma unroll
    for (int t = 0; t < 2; t++) {
        float r0 = rs[t][0], r1 = rs[t][1];
        r0 += __shfl_xor_sync(0xffffffffu, r0, 1);
        r0 += __shfl_xor_sync(0xffffffffu, r0, 2);
        r1 += __shfl_xor_sync(0xffffffffu, r1, 1);
        r1 += __shfl_xor_sync(0xffffffffu, r1, 2);
        const float inv0 = 1.0f / r0, inv1 = 1.0f / r1;
        const int s_lo = q0 + wid*32 + t*16 + gid;
        #pragma unroll
        for (int n = 0; n < 8; n++) {
            int d = h*64 + n*8 + 2*tig;
            *(__half2*)&g_ao[(size_t)(b*SEQ + s_lo    ) * DM + d] =
                __floats2half2_rn(O[t][n][0] * inv0, O[t][n][1] * inv0);
            *(__half2*)&g_ao[(size_t)(b*SEQ + s_lo + 8) * DM + d] =
                __floats2half2_rn(O[t][n][2] * inv1, O[t][n][3] * inv1);
        }
    }
}

// ---------------------------------------------------------------------------
extern "C" void kernel_launch(void* const* d_in, const int* in_sizes, int n_in,
                              void* d_out, int out_size)
{
    const float* x    = (const float*)d_in[0];
    const float* Wqkv = (const float*)d_in[1];
    const float* bqkv = (const float*)d_in[2];
    const float* Wout = (const float*)d_in[3];
    const float* bout = (const float*)d_in[4];
    float* out = (float*)d_out;

    cudaFuncSetAttribute(qkv_kernel,
                         cudaFuncAttributeMaxDynamicSharedMemorySize, GEMM_SMEM);
    cudaFuncSetAttribute(out_kernel,
                         cudaFuncAttributeMaxDynamicSharedMemorySize, GEMM_SMEM);
    cudaFuncSetAttribute(flash_kernel,
                         cudaFuncAttributeMaxDynamicSharedMemorySize, FL_SMEM);

    init_kernel<<<INIT_BLOCKS, 256>>>(
        (const float4*)x, (const float4*)Wqkv, (const float4*)Wout);
    qkv_kernel<<<dim3(24, 64), 256, GEMM_SMEM>>>(bqkv);
    flash_kernel<<<dim3(SEQ / 256, 64), 256, FL_SMEM>>>();
    out_kernel<<<dim3(8, 64), 256, GEMM_SMEM>>>(bout, out);
}